// round 2
// baseline (speedup 1.0000x reference)
#include <cuda_runtime.h>
#include <math.h>

#define DIMV 1024
#define NH 16
#define HD 64
#define BB 2
#define SS 2048
#define MTOT (BB*SS)

// Scratch: Q/K/V in [B,H,S,hd] layout, attention output in [B,S,DIM] layout.
__device__ float g_q[BB*NH*SS*HD];
__device__ float g_k[BB*NH*SS*HD];
__device__ float g_v[BB*NH*SS*HD];
__device__ float g_att[BB*SS*DIMV];

// ---------------------------------------------------------------------------
// Tiled SGEMM: C[M,N] = A[M,K] @ B[K,N] + bias[N]
// BM=BN=128, BK=8, 256 threads, 8x8 microtile.
// MODE 0: scatter epilogue -> g_q/g_k/g_v in [B,H,S,hd] layout
// MODE 1: plain row-major store to C
// ---------------------------------------------------------------------------
template<int MODE>
__global__ __launch_bounds__(256)
void sgemm_kernel(const float* __restrict__ A, const float* __restrict__ Bm,
                  const float* __restrict__ bias, float* __restrict__ C,
                  int M, int N, int K)
{
    __shared__ float As[8][128];
    __shared__ float Bs[8][128];

    const int tid = threadIdx.x;
    const int bm = blockIdx.y * 128;
    const int bn = blockIdx.x * 128;

    const int a_row = tid >> 1;
    const int a_col = (tid & 1) * 4;
    const int b_row = tid >> 5;
    const int b_col = (tid & 31) * 4;

    const int ty = tid >> 4;   // 0..15
    const int tx = tid & 15;   // 0..15

    float acc[8][8];
#pragma unroll
    for (int i = 0; i < 8; i++)
#pragma unroll
        for (int j = 0; j < 8; j++) acc[i][j] = 0.f;

    const float* Aptr = A + (size_t)(bm + a_row) * K + a_col;
    const float* Bptr = Bm + (size_t)b_row * N + bn + b_col;

    for (int k0 = 0; k0 < K; k0 += 8) {
        float4 av = *(const float4*)(Aptr + k0);
        As[a_col + 0][a_row] = av.x;
        As[a_col + 1][a_row] = av.y;
        As[a_col + 2][a_row] = av.z;
        As[a_col + 3][a_row] = av.w;
        float4 bv = *(const float4*)(Bptr + (size_t)k0 * N);
        *(float4*)&Bs[b_row][b_col] = bv;
        __syncthreads();

#pragma unroll
        for (int kk = 0; kk < 8; kk++) {
            float ar[8], br[8];
            *(float4*)&ar[0] = *(const float4*)&As[kk][ty * 8];
            *(float4*)&ar[4] = *(const float4*)&As[kk][ty * 8 + 4];
            *(float4*)&br[0] = *(const float4*)&Bs[kk][tx * 8];
            *(float4*)&br[4] = *(const float4*)&Bs[kk][tx * 8 + 4];
#pragma unroll
            for (int i = 0; i < 8; i++)
#pragma unroll
                for (int j = 0; j < 8; j++)
                    acc[i][j] = fmaf(ar[i], br[j], acc[i][j]);
        }
        __syncthreads();
    }

#pragma unroll
    for (int i = 0; i < 8; i++) {
        const int m = bm + ty * 8 + i;
#pragma unroll
        for (int j = 0; j < 8; j++) {
            const int n = bn + tx * 8 + j;
            float val = acc[i][j] + bias[n];
            if (MODE == 0) {
                // n -> (which, h, d); m -> (b, s)
                const int which = n >> 10;
                const int hw = n & 1023;
                const int h = hw >> 6;
                const int d = hw & 63;
                const int b = m >> 11;
                const int s = m & 2047;
                float* dst = (which == 0) ? g_q : (which == 1) ? g_k : g_v;
                dst[(((size_t)(b * NH + h)) * SS + s) * HD + d] = val;
            } else {
                C[(size_t)m * N + n] = val;
            }
        }
    }
}

// ---------------------------------------------------------------------------
// Flash attention fp32: per block one (b, h, 64-query tile).
// 256 threads (16x16), 4x4 microtiles, online softmax.
// smem: Qt[64][64] (d-major, pre-scaled), Kd[64][64] (d-major),
//       Vs[64][64] (key-major), Pt[64][65] (key-major, padded),
//       red[64][16], row_m/row_l/row_a[64]
// ---------------------------------------------------------------------------
#define FLASH_SMEM_FLOATS (3*64*64 + 64*65 + 64*16 + 3*64)
#define FLASH_SMEM_BYTES  (FLASH_SMEM_FLOATS * 4)

__global__ __launch_bounds__(256)
void flash_attn_kernel(const float* __restrict__ Qg, const float* __restrict__ Kg,
                       const float* __restrict__ Vg, float* __restrict__ Og)
{
    extern __shared__ float sm[];
    float* Qt    = sm;                  // [64][64]
    float* Kd    = Qt + 64 * 64;        // [64][64]
    float* Vs    = Kd + 64 * 64;        // [64][64]
    float* Pt    = Vs + 64 * 64;        // [64][65]
    float* red   = Pt + 64 * 65;        // [64][16]
    float* row_m = red + 64 * 16;       // [64]
    float* row_l = row_m + 64;          // [64]
    float* row_a = row_l + 64;          // [64]

    const int tid = threadIdx.x;
    const int tx = tid & 15;
    const int ty = tid >> 4;

    const int qt = blockIdx.x;
    const int h  = blockIdx.y;
    const int b  = blockIdx.z;

    const float* Qp = Qg + (((size_t)(b * NH + h)) * SS + qt * 64) * HD;
    const float* Kp = Kg + ((size_t)(b * NH + h)) * SS * HD;
    const float* Vp = Vg + ((size_t)(b * NH + h)) * SS * HD;

    const float SCALE = 0.125f;  // 1/sqrt(64)

    // Load Q tile transposed (d-major), folding in softmax scale.
#pragma unroll
    for (int r = 0; r < 4; r++) {
        int idx = tid + r * 256;        // float4 index, 0..1023
        int q  = idx >> 4;
        int d4 = (idx & 15) * 4;
        float4 v = *(const float4*)(Qp + q * HD + d4);
        Qt[(d4 + 0) * 64 + q] = v.x * SCALE;
        Qt[(d4 + 1) * 64 + q] = v.y * SCALE;
        Qt[(d4 + 2) * 64 + q] = v.z * SCALE;
        Qt[(d4 + 3) * 64 + q] = v.w * SCALE;
    }
    if (tid < 64) { row_m[tid] = -1e30f; row_l[tid] = 0.f; }

    float Oa[4][4];
#pragma unroll
    for (int i = 0; i < 4; i++)
#pragma unroll
        for (int j = 0; j < 4; j++) Oa[i][j] = 0.f;

    __syncthreads();

    for (int kt = 0; kt < SS / 64; kt++) {
        const float* Ktile = Kp + (size_t)kt * 64 * HD;
        const float* Vtile = Vp + (size_t)kt * 64 * HD;

        // Load K (transposed to d-major) and V (key-major).
#pragma unroll
        for (int r = 0; r < 4; r++) {
            int idx = tid + r * 256;
            int key = idx >> 4;
            int d4  = (idx & 15) * 4;
            float4 kv = *(const float4*)(Ktile + key * HD + d4);
            Kd[(d4 + 0) * 64 + key] = kv.x;
            Kd[(d4 + 1) * 64 + key] = kv.y;
            Kd[(d4 + 2) * 64 + key] = kv.z;
            Kd[(d4 + 3) * 64 + key] = kv.w;
            float4 vv = *(const float4*)(Vtile + key * HD + d4);
            *(float4*)&Vs[key * 64 + d4] = vv;
        }
        __syncthreads();

        // Sc[4q][4k] = (Q*scale) @ K^T over d
        float Sc[4][4];
#pragma unroll
        for (int i = 0; i < 4; i++)
#pragma unroll
            for (int j = 0; j < 4; j++) Sc[i][j] = 0.f;

#pragma unroll 4
        for (int d = 0; d < 64; d++) {
            float4 av = *(const float4*)&Qt[d * 64 + ty * 4];
            float4 bv = *(const float4*)&Kd[d * 64 + tx * 4];
            float ar[4] = {av.x, av.y, av.z, av.w};
            float br[4] = {bv.x, bv.y, bv.z, bv.w};
#pragma unroll
            for (int i = 0; i < 4; i++)
#pragma unroll
                for (int j = 0; j < 4; j++)
                    Sc[i][j] = fmaf(ar[i], br[j], Sc[i][j]);
        }

        // Partial row max -> red
#pragma unroll
        for (int i = 0; i < 4; i++) {
            float pm = Sc[i][0];
#pragma unroll
            for (int j = 1; j < 4; j++) pm = fmaxf(pm, Sc[i][j]);
            red[(ty * 4 + i) * 16 + tx] = pm;
        }
        __syncthreads();

        if (tid < 64) {
            float mx = red[tid * 16];
#pragma unroll
            for (int t = 1; t < 16; t++) mx = fmaxf(mx, red[tid * 16 + t]);
            float mo = row_m[tid];
            float mn = fmaxf(mo, mx);
            row_m[tid] = mn;
            float al = __expf(mo - mn);
            row_a[tid] = al;
            row_l[tid] *= al;
        }
        __syncthreads();

        // P = exp(Sc - m), store transposed Pt[key][q], row-sum partials
        float mn_i[4];
#pragma unroll
        for (int i = 0; i < 4; i++) mn_i[i] = row_m[ty * 4 + i];
#pragma unroll
        for (int i = 0; i < 4; i++) {
            float ps = 0.f;
#pragma unroll
            for (int j = 0; j < 4; j++) {
                float p = __expf(Sc[i][j] - mn_i[i]);
                ps += p;
                Pt[(tx * 4 + j) * 65 + (ty * 4 + i)] = p;
            }
            red[(ty * 4 + i) * 16 + tx] = ps;
        }
        // Rescale O accumulator while partial sums land
        float al_i[4];
#pragma unroll
        for (int i = 0; i < 4; i++) al_i[i] = row_a[ty * 4 + i];
#pragma unroll
        for (int i = 0; i < 4; i++)
#pragma unroll
            for (int j = 0; j < 4; j++) Oa[i][j] *= al_i[i];
        __syncthreads();

        if (tid < 64) {
            float s = 0.f;
#pragma unroll
            for (int t = 0; t < 16; t++) s += red[tid * 16 + t];
            row_l[tid] += s;
        }

        // O += P @ V over keys
#pragma unroll 2
        for (int key = 0; key < 64; key++) {
            float ar[4];
#pragma unroll
            for (int i = 0; i < 4; i++) ar[i] = Pt[key * 65 + ty * 4 + i];
            float4 bv = *(const float4*)&Vs[key * 64 + tx * 4];
            float br[4] = {bv.x, bv.y, bv.z, bv.w};
#pragma unroll
            for (int i = 0; i < 4; i++)
#pragma unroll
                for (int j = 0; j < 4; j++)
                    Oa[i][j] = fmaf(ar[i], br[j], Oa[i][j]);
        }
        __syncthreads();   // protect Kd/Vs/Pt/red for next tile; row_l done
    }

    // Finalize: divide by l, write [B,S,DIM] layout for out-proj GEMM.
    float li[4];
#pragma unroll
    for (int i = 0; i < 4; i++) li[i] = 1.f / row_l[ty * 4 + i];

#pragma unroll
    for (int i = 0; i < 4; i++) {
        int s = qt * 64 + ty * 4 + i;
        float* op = Og + ((size_t)(b * SS + s)) * DIMV + h * HD + tx * 4;
#pragma unroll
        for (int j = 0; j < 4; j++) op[j] = Oa[i][j] * li[i];
    }
}

// ---------------------------------------------------------------------------
extern "C" void kernel_launch(void* const* d_in, const int* in_sizes, int n_in,
                              void* d_out, int out_size)
{
    (void)in_sizes; (void)n_in; (void)out_size;
    const float* x     = (const float*)d_in[0];
    const float* W_qkv = (const float*)d_in[1];
    const float* b_qkv = (const float*)d_in[2];
    const float* W_out = (const float*)d_in[3];
    const float* b_out = (const float*)d_in[4];
    float* out = (float*)d_out;

    float *qb, *kb, *vb, *ab;
    cudaGetSymbolAddress((void**)&qb, g_q);
    cudaGetSymbolAddress((void**)&kb, g_k);
    cudaGetSymbolAddress((void**)&vb, g_v);
    cudaGetSymbolAddress((void**)&ab, g_att);

    // 1. QKV GEMM with head-layout scatter: [4096,1024] @ [1024,3072]
    {
        dim3 grid(3 * DIMV / 128, MTOT / 128);
        sgemm_kernel<0><<<grid, 256>>>(x, W_qkv, b_qkv, nullptr, MTOT, 3 * DIMV, DIMV);
    }

    // 2. Flash attention
    {
        static bool attr_set = false;
        if (!attr_set) {
            cudaFuncSetAttribute(flash_attn_kernel,
                                 cudaFuncAttributeMaxDynamicSharedMemorySize,
                                 FLASH_SMEM_BYTES);
            attr_set = true;
        }
        dim3 grid(SS / 64, NH, BB);
        flash_attn_kernel<<<grid, 256, FLASH_SMEM_BYTES>>>(qb, kb, vb, ab);
    }

    // 3. Output projection: [4096,1024] @ [1024,1024]
    {
        dim3 grid(DIMV / 128, MTOT / 128);
        sgemm_kernel<1><<<grid, 256>>>(ab, W_out, b_out, out, MTOT, DIMV, DIMV);
    }
}

// round 3
// speedup vs baseline: 3.5643x; 3.5643x over previous
#include <cuda_runtime.h>
#include <math.h>

#define DIMV 1024
#define NH 16
#define HD 64
#define BB 2
#define SS 2048
#define MTOT (BB*SS)

// Scratch: Q/K/V in [B,H,S,hd] layout, attention output in [B,S,DIM] layout.
__device__ float g_q[BB*NH*SS*HD];
__device__ float g_k[BB*NH*SS*HD];
__device__ float g_v[BB*NH*SS*HD];
__device__ float g_att[BB*SS*DIMV];

// ---------------------------------------------------------------------------
// helpers
// ---------------------------------------------------------------------------
__device__ __forceinline__ unsigned f2tf(float x) {
    unsigned u;
    asm("cvt.rna.tf32.f32 %0, %1;" : "=r"(u) : "f"(x));
    return u;
}
__device__ __forceinline__ float ex2f(float x) {
    float y;
    asm("ex2.approx.f32 %0, %1;" : "=f"(y) : "f"(x));
    return y;
}
// D = A(16x8,row) * B(8x8,col) + D, tf32 inputs, f32 accum
__device__ __forceinline__ void mma_tf32(float* c, const unsigned* a, const unsigned* b) {
    asm volatile(
        "mma.sync.aligned.m16n8k8.row.col.f32.tf32.tf32.f32 "
        "{%0,%1,%2,%3}, {%4,%5,%6,%7}, {%8,%9}, {%0,%1,%2,%3};"
        : "+f"(c[0]), "+f"(c[1]), "+f"(c[2]), "+f"(c[3])
        : "r"(a[0]), "r"(a[1]), "r"(a[2]), "r"(a[3]), "r"(b[0]), "r"(b[1]));
}

// ---------------------------------------------------------------------------
// TF32 tensor-core GEMM: C[M,N] = A[M,K] @ B[K,N] + bias[N]
// BM=128, BN=128, BK=16, 256 threads (8 warps: 4 along M x 2 along N),
// warp tile 32x64 (2 m-tiles x 8 n-tiles of m16n8k8). Double-buffered smem.
// MODE 0: scatter epilogue -> g_q/g_k/g_v in [B,H,S,hd]; MODE 1: row-major C.
// ---------------------------------------------------------------------------
#define APITCH 136
#define BPITCH 136

template<int MODE>
__global__ __launch_bounds__(256)
void sgemm_tf32(const float* __restrict__ A, const float* __restrict__ Bm,
                const float* __restrict__ bias, float* __restrict__ C,
                int M, int N, int K)
{
    __shared__ float At[2][16][APITCH];   // [k][m], tf32 bits
    __shared__ float Bs[2][16][BPITCH];   // [k][n], tf32 bits

    const int tid  = threadIdx.x;
    const int lane = tid & 31;
    const int w    = tid >> 5;
    const int g    = lane >> 2;   // groupID
    const int tig  = lane & 3;    // thread in group

    const int moff = 32 * (w & 3);
    const int noff = 64 * (w >> 2);

    const int bm = blockIdx.y * 128;
    const int bn = blockIdx.x * 128;

    float acc[2][8][4];
#pragma unroll
    for (int mt = 0; mt < 2; mt++)
#pragma unroll
        for (int nt = 0; nt < 8; nt++)
#pragma unroll
            for (int i = 0; i < 4; i++) acc[mt][nt][i] = 0.f;

    // gmem staging regs
    float4 a4[2], b4[2];
    // A tile: 128 rows x 16 k -> 512 float4; B tile: 16 k x 128 n -> 512 float4
    const int am  = (tid * 2 + 0) >> 2;        // reorganize: idx = tid + r*256
    (void)am;

    auto ldg_tiles = [&](int k0) {
#pragma unroll
        for (int r = 0; r < 2; r++) {
            int idx = tid + r * 256;           // 0..511
            int arow = idx >> 2;               // m 0..127
            int ac4  = (idx & 3) * 4;          // k 0,4,8,12
            a4[r] = *(const float4*)(A + (size_t)(bm + arow) * K + k0 + ac4);
            int brow = idx >> 5;               // k 0..15
            int bc4  = (idx & 31) * 4;         // n
            b4[r] = *(const float4*)(Bm + (size_t)(k0 + brow) * N + bn + bc4);
        }
    };
    auto sts_tiles = [&](int buf) {
#pragma unroll
        for (int r = 0; r < 2; r++) {
            int idx = tid + r * 256;
            int arow = idx >> 2;
            int ac4  = (idx & 3) * 4;
            At[buf][ac4 + 0][arow] = __uint_as_float(f2tf(a4[r].x));
            At[buf][ac4 + 1][arow] = __uint_as_float(f2tf(a4[r].y));
            At[buf][ac4 + 2][arow] = __uint_as_float(f2tf(a4[r].z));
            At[buf][ac4 + 3][arow] = __uint_as_float(f2tf(a4[r].w));
            int brow = idx >> 5;
            int bc4  = (idx & 31) * 4;
            Bs[buf][brow][bc4 + 0] = __uint_as_float(f2tf(b4[r].x));
            Bs[buf][brow][bc4 + 1] = __uint_as_float(f2tf(b4[r].y));
            Bs[buf][brow][bc4 + 2] = __uint_as_float(f2tf(b4[r].z));
            Bs[buf][brow][bc4 + 3] = __uint_as_float(f2tf(b4[r].w));
        }
    };

    const int iters = K >> 4;
    ldg_tiles(0);
    sts_tiles(0);
    __syncthreads();

    for (int it = 0; it < iters; it++) {
        const int cur = it & 1;
        if (it + 1 < iters) ldg_tiles((it + 1) << 4);

#pragma unroll
        for (int ks = 0; ks < 2; ks++) {
            unsigned af[2][4], bf[8][2];
#pragma unroll
            for (int mt = 0; mt < 2; mt++) {
                const float* base = &At[cur][ks * 8 + tig][moff + 16 * mt + g];
                af[mt][0] = __float_as_uint(base[0]);
                af[mt][1] = __float_as_uint(base[8]);
                const float* base2 = &At[cur][ks * 8 + tig + 4][moff + 16 * mt + g];
                af[mt][2] = __float_as_uint(base2[0]);
                af[mt][3] = __float_as_uint(base2[8]);
            }
#pragma unroll
            for (int nt = 0; nt < 8; nt++) {
                bf[nt][0] = __float_as_uint(Bs[cur][ks * 8 + tig][noff + 8 * nt + g]);
                bf[nt][1] = __float_as_uint(Bs[cur][ks * 8 + tig + 4][noff + 8 * nt + g]);
            }
#pragma unroll
            for (int mt = 0; mt < 2; mt++)
#pragma unroll
                for (int nt = 0; nt < 8; nt++)
                    mma_tf32(acc[mt][nt], af[mt], bf[nt]);
        }
        if (it + 1 < iters) sts_tiles(cur ^ 1);
        __syncthreads();
    }

    // epilogue
#pragma unroll
    for (int mt = 0; mt < 2; mt++) {
#pragma unroll
        for (int nt = 0; nt < 8; nt++) {
            const int n = bn + noff + 8 * nt + 2 * tig;
            const float bz0 = bias[n], bz1 = bias[n + 1];
#pragma unroll
            for (int half = 0; half < 2; half++) {
                const int m = bm + moff + 16 * mt + g + half * 8;
                float v0 = acc[mt][nt][half * 2 + 0] + bz0;
                float v1 = acc[mt][nt][half * 2 + 1] + bz1;
                if (MODE == 0) {
                    const int which = n >> 10;
                    const int hw = n & 1023;
                    const int h = hw >> 6;
                    const int d = hw & 63;
                    const int b = m >> 11;
                    const int s = m & 2047;
                    float* dst = (which == 0) ? g_q : (which == 1) ? g_k : g_v;
                    float2* p = (float2*)&dst[(((size_t)(b * NH + h)) * SS + s) * HD + d];
                    *p = make_float2(v0, v1);
                } else {
                    float2* p = (float2*)&C[(size_t)m * N + n];
                    *p = make_float2(v0, v1);
                }
            }
        }
    }
}

// ---------------------------------------------------------------------------
// Flash attention, TF32 tensor cores.
// CTA: 128 q-rows x full hd=64, 8 warps (16 q-rows each), key tiles of 64.
// Softmax in log2 domain (scale includes log2(e)); online max/sum in regs.
// smem: Qs[128][68] Ks[64][68] Vs[64][72] Ps[128][68]  (tf32 bits) = 103 KB.
// ---------------------------------------------------------------------------
#define QP 68
#define KP 68
#define VP 72
#define PP 68
#define FLASH_SMEM_BYTES ((128*QP + 64*KP + 64*VP + 128*PP) * 4)

__global__ __launch_bounds__(256)
void flash_tf32(const float* __restrict__ Qg, const float* __restrict__ Kg,
                const float* __restrict__ Vg, float* __restrict__ Og)
{
    extern __shared__ float sm[];
    float* Qs = sm;                   // [128][QP]
    float* Ks = Qs + 128 * QP;        // [64][KP]
    float* Vs = Ks + 64 * KP;         // [64][VP]
    float* Ps = Vs + 64 * VP;         // [128][PP]

    const int tid  = threadIdx.x;
    const int lane = tid & 31;
    const int w    = tid >> 5;
    const int g    = lane >> 2;
    const int tig  = lane & 3;

    const int qt = blockIdx.x;
    const int h  = blockIdx.y;
    const int b  = blockIdx.z;

    const float* Qp = Qg + (((size_t)(b * NH + h)) * SS + qt * 128) * HD;
    const float* Kp = Kg + ((size_t)(b * NH + h)) * SS * HD;
    const float* Vp = Vg + ((size_t)(b * NH + h)) * SS * HD;

    const float SCALE = 0.125f * 1.44269504088896f;  // 1/sqrt(64) * log2(e)

    // ---- load Q (scaled, tf32) ----
#pragma unroll
    for (int r = 0; r < 8; r++) {
        int idx = tid + r * 256;      // 0..2047 float4s
        int row = idx >> 4;
        int c4  = (idx & 15) * 4;
        float4 v = *(const float4*)(Qp + row * HD + c4);
        Qs[row * QP + c4 + 0] = __uint_as_float(f2tf(v.x * SCALE));
        Qs[row * QP + c4 + 1] = __uint_as_float(f2tf(v.y * SCALE));
        Qs[row * QP + c4 + 2] = __uint_as_float(f2tf(v.z * SCALE));
        Qs[row * QP + c4 + 3] = __uint_as_float(f2tf(v.w * SCALE));
    }
    __syncthreads();

    // ---- cache Q fragments: rows [16w, 16w+16) ----
    unsigned qf[8][4];
#pragma unroll
    for (int ks = 0; ks < 8; ks++) {
        const int r0 = (16 * w + g) * QP;
        const int r1 = (16 * w + g + 8) * QP;
        qf[ks][0] = __float_as_uint(Qs[r0 + ks * 8 + tig]);
        qf[ks][1] = __float_as_uint(Qs[r1 + ks * 8 + tig]);
        qf[ks][2] = __float_as_uint(Qs[r0 + ks * 8 + tig + 4]);
        qf[ks][3] = __float_as_uint(Qs[r1 + ks * 8 + tig + 4]);
    }

    float m0 = -1e30f, m1 = -1e30f, l0 = 0.f, l1 = 0.f;
    float Oa[8][4];
#pragma unroll
    for (int dt = 0; dt < 8; dt++)
#pragma unroll
        for (int i = 0; i < 4; i++) Oa[dt][i] = 0.f;

    // prefetch key tile 0 (4 float4 each of K and V per thread)
    float4 kreg[4], vreg[4];
#pragma unroll
    for (int r = 0; r < 4; r++) {
        int idx = tid + r * 256;      // 0..1023
        int row = idx >> 4;
        int c4  = (idx & 15) * 4;
        kreg[r] = *(const float4*)(Kp + row * HD + c4);
        vreg[r] = *(const float4*)(Vp + row * HD + c4);
    }

    for (int kt = 0; kt < SS / 64; kt++) {
        __syncthreads();  // previous tile's reads complete
#pragma unroll
        for (int r = 0; r < 4; r++) {
            int idx = tid + r * 256;
            int row = idx >> 4;
            int c4  = (idx & 15) * 4;
            Ks[row * KP + c4 + 0] = __uint_as_float(f2tf(kreg[r].x));
            Ks[row * KP + c4 + 1] = __uint_as_float(f2tf(kreg[r].y));
            Ks[row * KP + c4 + 2] = __uint_as_float(f2tf(kreg[r].z));
            Ks[row * KP + c4 + 3] = __uint_as_float(f2tf(kreg[r].w));
            Vs[row * VP + c4 + 0] = __uint_as_float(f2tf(vreg[r].x));
            Vs[row * VP + c4 + 1] = __uint_as_float(f2tf(vreg[r].y));
            Vs[row * VP + c4 + 2] = __uint_as_float(f2tf(vreg[r].z));
            Vs[row * VP + c4 + 3] = __uint_as_float(f2tf(vreg[r].w));
        }
        __syncthreads();

        if (kt + 1 < SS / 64) {
            const float* Kn = Kp + (size_t)(kt + 1) * 64 * HD;
            const float* Vn = Vp + (size_t)(kt + 1) * 64 * HD;
#pragma unroll
            for (int r = 0; r < 4; r++) {
                int idx = tid + r * 256;
                int row = idx >> 4;
                int c4  = (idx & 15) * 4;
                kreg[r] = *(const float4*)(Kn + row * HD + c4);
                vreg[r] = *(const float4*)(Vn + row * HD + c4);
            }
        }

        // ---- S = Q @ K^T (log2-scaled) ----
        float S[8][4];
#pragma unroll
        for (int nt = 0; nt < 8; nt++)
#pragma unroll
            for (int i = 0; i < 4; i++) S[nt][i] = 0.f;
#pragma unroll
        for (int ks = 0; ks < 8; ks++) {
#pragma unroll
            for (int nt = 0; nt < 8; nt++) {
                unsigned bf[2];
                const float* kb = &Ks[(8 * nt + g) * KP + ks * 8 + tig];
                bf[0] = __float_as_uint(kb[0]);
                bf[1] = __float_as_uint(kb[4]);
                mma_tf32(S[nt], qf[ks], bf);
            }
        }

        // ---- online softmax (rows g and g+8 of this warp's 16) ----
        float mx0 = S[0][0], mx1 = S[0][2];
#pragma unroll
        for (int nt = 0; nt < 8; nt++) {
            mx0 = fmaxf(mx0, fmaxf(S[nt][0], S[nt][1]));
            mx1 = fmaxf(mx1, fmaxf(S[nt][2], S[nt][3]));
        }
        mx0 = fmaxf(mx0, __shfl_xor_sync(0xffffffffu, mx0, 1));
        mx0 = fmaxf(mx0, __shfl_xor_sync(0xffffffffu, mx0, 2));
        mx1 = fmaxf(mx1, __shfl_xor_sync(0xffffffffu, mx1, 1));
        mx1 = fmaxf(mx1, __shfl_xor_sync(0xffffffffu, mx1, 2));

        const float mn0 = fmaxf(m0, mx0);
        const float mn1 = fmaxf(m1, mx1);
        const float al0 = ex2f(m0 - mn0);
        const float al1 = ex2f(m1 - mn1);
        m0 = mn0; m1 = mn1;

        float sum0 = 0.f, sum1 = 0.f;
        const int pr0 = (16 * w + g) * PP;
        const int pr1 = (16 * w + g + 8) * PP;
#pragma unroll
        for (int nt = 0; nt < 8; nt++) {
            float p0 = ex2f(S[nt][0] - mn0);
            float p1 = ex2f(S[nt][1] - mn0);
            float p2 = ex2f(S[nt][2] - mn1);
            float p3 = ex2f(S[nt][3] - mn1);
            sum0 += p0 + p1;
            sum1 += p2 + p3;
            float2* w0 = (float2*)&Ps[pr0 + 8 * nt + 2 * tig];
            *w0 = make_float2(__uint_as_float(f2tf(p0)), __uint_as_float(f2tf(p1)));
            float2* w1 = (float2*)&Ps[pr1 + 8 * nt + 2 * tig];
            *w1 = make_float2(__uint_as_float(f2tf(p2)), __uint_as_float(f2tf(p3)));
        }
        sum0 += __shfl_xor_sync(0xffffffffu, sum0, 1);
        sum0 += __shfl_xor_sync(0xffffffffu, sum0, 2);
        sum1 += __shfl_xor_sync(0xffffffffu, sum1, 1);
        sum1 += __shfl_xor_sync(0xffffffffu, sum1, 2);
        l0 = l0 * al0 + sum0;
        l1 = l1 * al1 + sum1;

#pragma unroll
        for (int dt = 0; dt < 8; dt++) {
            Oa[dt][0] *= al0; Oa[dt][1] *= al0;
            Oa[dt][2] *= al1; Oa[dt][3] *= al1;
        }
        __syncwarp();

        // ---- P fragments ----
        unsigned pf[8][4];
#pragma unroll
        for (int ks = 0; ks < 8; ks++) {
            pf[ks][0] = __float_as_uint(Ps[pr0 + ks * 8 + tig]);
            pf[ks][1] = __float_as_uint(Ps[pr1 + ks * 8 + tig]);
            pf[ks][2] = __float_as_uint(Ps[pr0 + ks * 8 + tig + 4]);
            pf[ks][3] = __float_as_uint(Ps[pr1 + ks * 8 + tig + 4]);
        }

        // ---- O += P @ V ----
#pragma unroll
        for (int ks = 0; ks < 8; ks++) {
#pragma unroll
            for (int dt = 0; dt < 8; dt++) {
                unsigned bf[2];
                bf[0] = __float_as_uint(Vs[(ks * 8 + tig) * VP + 8 * dt + g]);
                bf[1] = __float_as_uint(Vs[(ks * 8 + tig + 4) * VP + 8 * dt + g]);
                mma_tf32(Oa[dt], pf[ks], bf);
            }
        }
    }

    // ---- finalize & write [B,S,DIM] ----
    const float li0 = 1.f / l0;
    const float li1 = 1.f / l1;
    const int s0 = qt * 128 + 16 * w + g;
    const int s1 = s0 + 8;
#pragma unroll
    for (int dt = 0; dt < 8; dt++) {
        const int col = h * HD + 8 * dt + 2 * tig;
        float2* p0 = (float2*)&Og[((size_t)(b * SS + s0)) * DIMV + col];
        *p0 = make_float2(Oa[dt][0] * li0, Oa[dt][1] * li0);
        float2* p1 = (float2*)&Og[((size_t)(b * SS + s1)) * DIMV + col];
        *p1 = make_float2(Oa[dt][2] * li1, Oa[dt][3] * li1);
    }
}

// ---------------------------------------------------------------------------
extern "C" void kernel_launch(void* const* d_in, const int* in_sizes, int n_in,
                              void* d_out, int out_size)
{
    (void)in_sizes; (void)n_in; (void)out_size;
    const float* x     = (const float*)d_in[0];
    const float* W_qkv = (const float*)d_in[1];
    const float* b_qkv = (const float*)d_in[2];
    const float* W_out = (const float*)d_in[3];
    const float* b_out = (const float*)d_in[4];
    float* out = (float*)d_out;

    float *qb, *kb, *vb, *ab;
    cudaGetSymbolAddress((void**)&qb, g_q);
    cudaGetSymbolAddress((void**)&kb, g_k);
    cudaGetSymbolAddress((void**)&vb, g_v);
    cudaGetSymbolAddress((void**)&ab, g_att);

    // 1. QKV GEMM with head-layout scatter: [4096,1024] @ [1024,3072]
    {
        dim3 grid(3 * DIMV / 128, MTOT / 128);
        sgemm_tf32<0><<<grid, 256>>>(x, W_qkv, b_qkv, nullptr, MTOT, 3 * DIMV, DIMV);
    }

    // 2. Flash attention (TF32 MMA)
    {
        static bool attr_set = false;
        if (!attr_set) {
            cudaFuncSetAttribute(flash_tf32,
                                 cudaFuncAttributeMaxDynamicSharedMemorySize,
                                 FLASH_SMEM_BYTES);
            attr_set = true;
        }
        dim3 grid(SS / 128, NH, BB);
        flash_tf32<<<grid, 256, FLASH_SMEM_BYTES>>>(qb, kb, vb, ab);
    }

    // 3. Output projection: [4096,1024] @ [1024,1024]
    {
        dim3 grid(DIMV / 128, MTOT / 128);
        sgemm_tf32<1><<<grid, 256>>>(ab, W_out, b_out, out, MTOT, DIMV, DIMV);
    }
}

// round 9
// speedup vs baseline: 6.2126x; 1.7430x over previous
#include <cuda_runtime.h>
#include <cuda_fp16.h>
#include <math.h>

#define DIMV 1024
#define NH 16
#define HD 64
#define BB 2
#define SS 2048
#define MTOT (BB*SS)

// Scratch. Q/K as fp16 [b,h,s,d]; V as fp16 transposed [b,h,d,s]; attn out fp32 [b,s,dim].
__device__ __half g_q [BB*NH*SS*HD];
__device__ __half g_k [BB*NH*SS*HD];
__device__ __half g_vt[BB*NH*HD*SS];
__device__ float  g_att[BB*SS*DIMV];

// ---------------------------------------------------------------------------
// helpers
// ---------------------------------------------------------------------------
__device__ __forceinline__ float ex2f(float x) {
    float y;
    asm("ex2.approx.f32 %0, %1;" : "=f"(y) : "f"(x));
    return y;
}
__device__ __forceinline__ unsigned pack2(float a, float b) {
    __half2 h = __floats2half2_rn(a, b);
    return *(unsigned*)&h;
}
// D = A(16x16,row) * B(16x8,col) + D, f16 in, f32 accum
__device__ __forceinline__ void mma_f16(float* c, const unsigned* a, const unsigned* b) {
    asm volatile(
        "mma.sync.aligned.m16n8k16.row.col.f32.f16.f16.f32 "
        "{%0,%1,%2,%3}, {%4,%5,%6,%7}, {%8,%9}, {%0,%1,%2,%3};"
        : "+f"(c[0]), "+f"(c[1]), "+f"(c[2]), "+f"(c[3])
        : "r"(a[0]), "r"(a[1]), "r"(a[2]), "r"(a[3]), "r"(b[0]), "r"(b[1]));
}

// GEMM smem: 16 halves/row (32B), 8B-chunk XOR swizzle -> conflict-free frag LDS.
__device__ __forceinline__ int gsw(int r, int k) {
    int x = ((r >> 1) ^ (r >> 3)) & 3;
    return r * 16 + (k & 3) + ((((k >> 2) ^ x)) & 3) * 4;
}
// Flash smem: 64 halves/row (128B), 16B-chunk XOR swizzle.
__device__ __forceinline__ int fsw(int r, int k) {
    return r * 64 + (k & 7) + ((((k >> 3) ^ r) & 7)) * 8;
}

// ---------------------------------------------------------------------------
// fp16 tensor-core GEMM: C[M,N] = A[M,K] @ B[K,N] + bias[N]  (A,B fp32 in gmem)
// BM=BN=128, BK=16, 256 threads (8 warps: 4 M x 2 N), warp tile 32x64.
// MODE 0: epilogue -> g_q/g_k fp16 [b,h,s,d], g_vt fp16 [b,h,d,s]
// MODE 1: row-major fp32 C.
// ---------------------------------------------------------------------------
template<int MODE>
__global__ __launch_bounds__(256)
void gemm_f16(const float* __restrict__ A, const float* __restrict__ Bm,
              const float* __restrict__ bias, float* __restrict__ C,
              int M, int N, int K)
{
    __shared__ __half As[2][128 * 16];
    __shared__ __half Bs[2][128 * 16];

    const int tid  = threadIdx.x;
    const int lane = tid & 31;
    const int w    = tid >> 5;
    const int g    = lane >> 2;
    const int tig  = lane & 3;

    const int moff = 32 * (w & 3);
    const int noff = 64 * (w >> 2);

    const int bm = blockIdx.y * 128;
    const int bn = blockIdx.x * 128;

    float acc[2][8][4];
#pragma unroll
    for (int mt = 0; mt < 2; mt++)
#pragma unroll
        for (int nt = 0; nt < 8; nt++)
#pragma unroll
            for (int i = 0; i < 4; i++) acc[mt][nt][i] = 0.f;

    float4 a4[2];
    float  bg[2][4];

    auto ldg_tiles = [&](int k0) {
#pragma unroll
        for (int r = 0; r < 2; r++) {
            int idx  = tid + r * 256;            // 0..511
            int arow = idx >> 2;                 // m
            int ac4  = (idx & 3) * 4;            // k
            a4[r] = *(const float4*)(A + (size_t)(bm + arow) * K + k0 + ac4);
            int n  = idx & 127;
            int kq = idx >> 7;                   // 0..3
#pragma unroll
            for (int j = 0; j < 4; j++)
                bg[r][j] = Bm[(size_t)(k0 + kq * 4 + j) * N + bn + n];
        }
    };
    auto sts_tiles = [&](int buf) {
#pragma unroll
        for (int r = 0; r < 2; r++) {
            int idx  = tid + r * 256;
            int arow = idx >> 2;
            int ac4  = (idx & 3) * 4;
            uint2 av = make_uint2(pack2(a4[r].x, a4[r].y), pack2(a4[r].z, a4[r].w));
            *(uint2*)&As[buf][gsw(arow, ac4)] = av;
            int n  = idx & 127;
            int kq = idx >> 7;
            uint2 bv = make_uint2(pack2(bg[r][0], bg[r][1]), pack2(bg[r][2], bg[r][3]));
            *(uint2*)&Bs[buf][gsw(n, kq * 4)] = bv;
        }
    };

    const int iters = K >> 4;
    ldg_tiles(0);
    sts_tiles(0);
    __syncthreads();

    for (int it = 0; it < iters; it++) {
        const int cur = it & 1;
        if (it + 1 < iters) ldg_tiles((it + 1) << 4);

        unsigned af[2][4], bf[8][2];
#pragma unroll
        for (int mt = 0; mt < 2; mt++) {
            const int m = moff + 16 * mt + g;
            af[mt][0] = *(const unsigned*)&As[cur][gsw(m,     2 * tig)];
            af[mt][1] = *(const unsigned*)&As[cur][gsw(m + 8, 2 * tig)];
            af[mt][2] = *(const unsigned*)&As[cur][gsw(m,     2 * tig + 8)];
            af[mt][3] = *(const unsigned*)&As[cur][gsw(m + 8, 2 * tig + 8)];
        }
#pragma unroll
        for (int nt = 0; nt < 8; nt++) {
            const int n = noff + 8 * nt + g;
            bf[nt][0] = *(const unsigned*)&Bs[cur][gsw(n, 2 * tig)];
            bf[nt][1] = *(const unsigned*)&Bs[cur][gsw(n, 2 * tig + 8)];
        }
#pragma unroll
        for (int mt = 0; mt < 2; mt++)
#pragma unroll
            for (int nt = 0; nt < 8; nt++)
                mma_f16(acc[mt][nt], af[mt], bf[nt]);

        if (it + 1 < iters) sts_tiles(cur ^ 1);
        __syncthreads();
    }

    // epilogue
#pragma unroll
    for (int mt = 0; mt < 2; mt++) {
#pragma unroll
        for (int nt = 0; nt < 8; nt++) {
            const int n = bn + noff + 8 * nt + 2 * tig;
            const float bz0 = bias[n], bz1 = bias[n + 1];
#pragma unroll
            for (int half_i = 0; half_i < 2; half_i++) {
                const int m = bm + moff + 16 * mt + g + half_i * 8;
                float v0 = acc[mt][nt][half_i * 2 + 0] + bz0;
                float v1 = acc[mt][nt][half_i * 2 + 1] + bz1;
                if (MODE == 0) {
                    const int which = n >> 10;
                    const int hw = n & 1023;
                    const int h = hw >> 6;
                    const int d = hw & 63;
                    const int b = m >> 11;
                    const int s = m & 2047;
                    if (which == 2) {
                        const size_t base = ((size_t)(b * NH + h) * HD + d) * SS + s;
                        g_vt[base]      = __float2half_rn(v0);
                        g_vt[base + SS] = __float2half_rn(v1);
                    } else {
                        __half* dst = (which == 0) ? g_q : g_k;
                        __half2* p = (__half2*)&dst[((size_t)(b * NH + h) * SS + s) * HD + d];
                        *p = __floats2half2_rn(v0, v1);
                    }
                } else {
                    float2* p = (float2*)&C[(size_t)m * N + n];
                    *p = make_float2(v0, v1);
                }
            }
        }
    }
}

// ---------------------------------------------------------------------------
// Flash attention, fp16 MMA. 128 q-rows/CTA, key tiles of 64, 8 warps.
// Q/K fp16 [b,h,s,d]; V fp16 transposed [b,h,d,s]. P stays in registers
// (QK^T C-fragment == PV A-fragment). Softmax in log2 domain.
// smem: Qs[128][64h] + Ks[64][64h] + Vs[64][64h] = 32KB static.
// ---------------------------------------------------------------------------
__global__ __launch_bounds__(256)
void flash_f16(const __half* __restrict__ Qg, const __half* __restrict__ Kg,
               const __half* __restrict__ Vtg, float* __restrict__ Og)
{
    __shared__ __half Qs[128 * 64];
    __shared__ __half Ks[64 * 64];
    __shared__ __half Vs[64 * 64];   // [d][key]

    const int tid  = threadIdx.x;
    const int lane = tid & 31;
    const int w    = tid >> 5;
    const int g    = lane >> 2;
    const int tig  = lane & 3;

    const int qt = blockIdx.x;
    const int h  = blockIdx.y;
    const int b  = blockIdx.z;

    const __half* Qp  = Qg  + ((size_t)(b * NH + h) * SS + qt * 128) * HD;
    const __half* Kp  = Kg  + (size_t)(b * NH + h) * SS * HD;
    const __half* Vtp = Vtg + (size_t)(b * NH + h) * HD * SS;

    // ---- load Q tile: 128 rows x 64 halves = 1024 uint4 -> 4 per thread ----
#pragma unroll
    for (int r = 0; r < 4; r++) {
        int idx = tid + r * 256;         // 0..1023 (16B units)
        int row = idx >> 3;              // 0..127
        int k8  = (idx & 7) * 8;
        uint4 v = *(const uint4*)&Qp[row * HD + k8];
        *(uint4*)&Qs[fsw(row, k8)] = v;
    }
    __syncthreads();

    // ---- cache Q fragments (rows 16w..16w+15) ----
    unsigned qf[4][4];
    const int qr0 = 16 * w + g;
#pragma unroll
    for (int dc = 0; dc < 4; dc++) {
        qf[dc][0] = *(const unsigned*)&Qs[fsw(qr0,     16 * dc + 2 * tig)];
        qf[dc][1] = *(const unsigned*)&Qs[fsw(qr0 + 8, 16 * dc + 2 * tig)];
        qf[dc][2] = *(const unsigned*)&Qs[fsw(qr0,     16 * dc + 2 * tig + 8)];
        qf[dc][3] = *(const unsigned*)&Qs[fsw(qr0 + 8, 16 * dc + 2 * tig + 8)];
    }

    const float SCALE = 0.125f * 1.44269504088896f;  // 1/sqrt(64) * log2(e)

    float m0 = -1e30f, m1 = -1e30f, l0 = 0.f, l1 = 0.f;
    float Oa[8][4];
#pragma unroll
    for (int dt = 0; dt < 8; dt++)
#pragma unroll
        for (int i = 0; i < 4; i++) Oa[dt][i] = 0.f;

    // prefetch tile 0 (K/V tiles are 64 rows x 64 halves = 512 uint4 -> 2/thread)
    uint4 kst[2], vst[2];
#pragma unroll
    for (int r = 0; r < 2; r++) {
        int idx = tid + r * 256;
        int row = idx >> 3;
        int k8  = (idx & 7) * 8;
        kst[r] = *(const uint4*)&Kp[row * HD + k8];
        vst[r] = *(const uint4*)&Vtp[(size_t)row * SS + k8];
    }

    for (int kt = 0; kt < SS / 64; kt++) {
        __syncthreads();
#pragma unroll
        for (int r = 0; r < 2; r++) {
            int idx = tid + r * 256;
            int row = idx >> 3;
            int k8  = (idx & 7) * 8;
            *(uint4*)&Ks[fsw(row, k8)] = kst[r];
            *(uint4*)&Vs[fsw(row, k8)] = vst[r];
        }
        __syncthreads();

        if (kt + 1 < SS / 64) {
            const __half* Kn = Kp + (size_t)(kt + 1) * 64 * HD;
#pragma unroll
            for (int r = 0; r < 2; r++) {
                int idx = tid + r * 256;
                int row = idx >> 3;
                int k8  = (idx & 7) * 8;
                kst[r] = *(const uint4*)&Kn[row * HD + k8];
                vst[r] = *(const uint4*)&Vtp[(size_t)row * SS + (kt + 1) * 64 + k8];
            }
        }

        // ---- S = Q @ K^T ----
        float S[8][4];
#pragma unroll
        for (int nt = 0; nt < 8; nt++)
#pragma unroll
            for (int i = 0; i < 4; i++) S[nt][i] = 0.f;
#pragma unroll
        for (int dc = 0; dc < 4; dc++) {
#pragma unroll
            for (int nt = 0; nt < 8; nt++) {
                unsigned bfr[2];
                bfr[0] = *(const unsigned*)&Ks[fsw(8 * nt + g, 16 * dc + 2 * tig)];
                bfr[1] = *(const unsigned*)&Ks[fsw(8 * nt + g, 16 * dc + 2 * tig + 8)];
                mma_f16(S[nt], qf[dc], bfr);
            }
        }

        // ---- online softmax (log2 domain, scale applied here) ----
        float mx0 = S[0][0], mx1 = S[0][2];
#pragma unroll
        for (int nt = 0; nt < 8; nt++) {
            mx0 = fmaxf(mx0, fmaxf(S[nt][0], S[nt][1]));
            mx1 = fmaxf(mx1, fmaxf(S[nt][2], S[nt][3]));
        }
        mx0 = fmaxf(mx0, __shfl_xor_sync(0xffffffffu, mx0, 1));
        mx0 = fmaxf(mx0, __shfl_xor_sync(0xffffffffu, mx0, 2));
        mx1 = fmaxf(mx1, __shfl_xor_sync(0xffffffffu, mx1, 1));
        mx1 = fmaxf(mx1, __shfl_xor_sync(0xffffffffu, mx1, 2));

        const float mn0 = fmaxf(m0, mx0 * SCALE);
        const float mn1 = fmaxf(m1, mx1 * SCALE);
        const float al0 = ex2f(m0 - mn0);
        const float al1 = ex2f(m1 - mn1);
        m0 = mn0; m1 = mn1;

        float sum0 = 0.f, sum1 = 0.f;
#pragma unroll
        for (int nt = 0; nt < 8; nt++) {
            float p0 = ex2f(S[nt][0] * SCALE - mn0);
            float p1 = ex2f(S[nt][1] * SCALE - mn0);
            float p2 = ex2f(S[nt][2] * SCALE - mn1);
            float p3 = ex2f(S[nt][3] * SCALE - mn1);
            sum0 += p0 + p1;
            sum1 += p2 + p3;
            S[nt][0] = p0; S[nt][1] = p1; S[nt][2] = p2; S[nt][3] = p3;
        }
        sum0 += __shfl_xor_sync(0xffffffffu, sum0, 1);
        sum0 += __shfl_xor_sync(0xffffffffu, sum0, 2);
        sum1 += __shfl_xor_sync(0xffffffffu, sum1, 1);
        sum1 += __shfl_xor_sync(0xffffffffu, sum1, 2);
        l0 = l0 * al0 + sum0;
        l1 = l1 * al1 + sum1;

#pragma unroll
        for (int dt = 0; dt < 8; dt++) {
            Oa[dt][0] *= al0; Oa[dt][1] *= al0;
            Oa[dt][2] *= al1; Oa[dt][3] *= al1;
        }

        // ---- O += P @ V  (P from registers: C-frag == A-frag) ----
#pragma unroll
        for (int kc = 0; kc < 4; kc++) {
            unsigned pf[4];
            pf[0] = pack2(S[2 * kc][0],     S[2 * kc][1]);
            pf[1] = pack2(S[2 * kc][2],     S[2 * kc][3]);
            pf[2] = pack2(S[2 * kc + 1][0], S[2 * kc + 1][1]);
            pf[3] = pack2(S[2 * kc + 1][2], S[2 * kc + 1][3]);
#pragma unroll
            for (int dt = 0; dt < 8; dt++) {
                unsigned bfr[2];
                bfr[0] = *(const unsigned*)&Vs[fsw(8 * dt + g, 16 * kc + 2 * tig)];
                bfr[1] = *(const unsigned*)&Vs[fsw(8 * dt + g, 16 * kc + 2 * tig + 8)];
                mma_f16(Oa[dt], pf, bfr);
            }
        }
    }

    // ---- finalize & write fp32 [B,S,DIM] ----
    const float li0 = 1.f / l0;
    const float li1 = 1.f / l1;
    const int s0 = qt * 128 + 16 * w + g;
    const int s1 = s0 + 8;
#pragma unroll
    for (int dt = 0; dt < 8; dt++) {
        const int col = h * HD + 8 * dt + 2 * tig;
        float2* p0 = (float2*)&Og[((size_t)(b * SS + s0)) * DIMV + col];
        *p0 = make_float2(Oa[dt][0] * li0, Oa[dt][1] * li0);
        float2* p1 = (float2*)&Og[((size_t)(b * SS + s1)) * DIMV + col];
        *p1 = make_float2(Oa[dt][2] * li1, Oa[dt][3] * li1);
    }
}

// ---------------------------------------------------------------------------
extern "C" void kernel_launch(void* const* d_in, const int* in_sizes, int n_in,
                              void* d_out, int out_size)
{
    (void)in_sizes; (void)n_in; (void)out_size;
    const float* x     = (const float*)d_in[0];
    const float* W_qkv = (const float*)d_in[1];
    const float* b_qkv = (const float*)d_in[2];
    const float* W_out = (const float*)d_in[3];
    const float* b_out = (const float*)d_in[4];
    float* out = (float*)d_out;

    __half *qb, *kb, *vtb;
    float  *ab;
    cudaGetSymbolAddress((void**)&qb,  g_q);
    cudaGetSymbolAddress((void**)&kb,  g_k);
    cudaGetSymbolAddress((void**)&vtb, g_vt);
    cudaGetSymbolAddress((void**)&ab,  g_att);

    // 1. QKV GEMM -> fp16 Q/K (head layout) + fp16 V^T
    {
        dim3 grid(3 * DIMV / 128, MTOT / 128);
        gemm_f16<0><<<grid, 256>>>(x, W_qkv, b_qkv, nullptr, MTOT, 3 * DIMV, DIMV);
    }
    // 2. Flash attention (fp16 MMA, register-resident P)
    {
        dim3 grid(SS / 128, NH, BB);
        flash_f16<<<grid, 256>>>(qb, kb, vtb, ab);
    }
    // 3. Output projection
    {
        dim3 grid(DIMV / 128, MTOT / 128);
        gemm_f16<1><<<grid, 256>>>(ab, W_out, b_out, out, MTOT, DIMV, DIMV);
    }
}

// round 11
// speedup vs baseline: 7.2790x; 1.1717x over previous
#include <cuda_runtime.h>
#include <cuda_fp16.h>
#include <math.h>

#define DIMV 1024
#define NH 16
#define HD 64
#define BB 2
#define SS 2048
#define MTOT (BB*SS)
#define KDIM 1024

// Scratch buffers.
__device__ __half g_xh  [MTOT*KDIM];        // x fp16 [M][K]
__device__ __half g_wqt [3*DIMV*KDIM];      // W_qkv^T fp16 [N=3072][K]
__device__ __half g_wot [DIMV*KDIM];        // W_out^T fp16 [N=1024][K]
__device__ __half g_q   [BB*NH*SS*HD];      // [b,h,s,d]
__device__ __half g_k   [BB*NH*SS*HD];      // [b,h,s,d]
__device__ __half g_vt  [BB*NH*HD*SS];      // [b,h,d,s]
__device__ __half g_atth[MTOT*DIMV];        // attention out fp16 [b*s][dim]

// ---------------------------------------------------------------------------
// helpers
// ---------------------------------------------------------------------------
__device__ __forceinline__ float ex2f(float x) {
    float y; asm("ex2.approx.f32 %0, %1;" : "=f"(y) : "f"(x)); return y;
}
__device__ __forceinline__ unsigned pack2(float a, float b) {
    __half2 h = __floats2half2_rn(a, b); return *(unsigned*)&h;
}
__device__ __forceinline__ void mma_f16(float* c, const unsigned* a, const unsigned* b) {
    asm volatile(
        "mma.sync.aligned.m16n8k16.row.col.f32.f16.f16.f32 "
        "{%0,%1,%2,%3}, {%4,%5,%6,%7}, {%8,%9}, {%0,%1,%2,%3};"
        : "+f"(c[0]), "+f"(c[1]), "+f"(c[2]), "+f"(c[3])
        : "r"(a[0]), "r"(a[1]), "r"(a[2]), "r"(a[3]), "r"(b[0]), "r"(b[1]));
}
// rows of 64 halves (128B), 16B-chunk XOR swizzle. Returns half-index.
__device__ __forceinline__ int fsw(int r, int k) {
    return r * 64 + (k & 7) + ((((k >> 3) ^ r) & 7)) * 8;
}
__device__ __forceinline__ unsigned smem_u32(const void* p) {
    unsigned a;
    asm("{ .reg .u64 t; cvta.to.shared.u64 t, %1; cvt.u32.u64 %0, t; }" : "=r"(a) : "l"(p));
    return a;
}
__device__ __forceinline__ void ldsm4(unsigned* r, unsigned addr) {
    asm volatile("ldmatrix.sync.aligned.m8n8.x4.shared.b16 {%0,%1,%2,%3}, [%4];"
                 : "=r"(r[0]), "=r"(r[1]), "=r"(r[2]), "=r"(r[3]) : "r"(addr));
}
// A-fragment (m16 x k16): regs = {mlo/klo, mhi/klo, mlo/khi, mhi/khi}
__device__ __forceinline__ void ldsmA(unsigned* r, unsigned tbase, int mbase, int kbase, int lane) {
    int row = mbase + (lane & 8) + (lane & 7);
    int col = kbase + (lane >> 4) * 8;
    ldsm4(r, tbase + 2 * fsw(row, col));
}
// B-fragment pair on [n][k] storage (n16 x k16):
// regs = {nlo/klo, nlo/khi, nhi/klo, nhi/khi} = {b0,b1 of nt_lo, b0,b1 of nt_hi}
__device__ __forceinline__ void ldsmB(unsigned* r, unsigned tbase, int nbase, int kbase, int lane) {
    int row = nbase + ((lane & 16) >> 1) + (lane & 7);
    int col = kbase + ((lane >> 3) & 1) * 8;
    ldsm4(r, tbase + 2 * fsw(row, col));
}

// ---------------------------------------------------------------------------
// Staging kernels
// ---------------------------------------------------------------------------
__global__ __launch_bounds__(256) void convert_x(const float* __restrict__ x, __half* __restrict__ xh) {
    int idx = blockIdx.x * 256 + threadIdx.x;      // float4 index
    float4 v = ((const float4*)x)[idx];
    ((uint2*)xh)[idx] = make_uint2(pack2(v.x, v.y), pack2(v.z, v.w));
}
// Wt[n][k] = W[k][n], fp16. Tile 32x32. grid (K/32, N/32), 256 threads.
__global__ __launch_bounds__(256) void transpose_w(const float* __restrict__ W, __half* __restrict__ Wt, int N) {
    __shared__ float t[32][33];
    const int tid = threadIdx.x;
    const int k0 = blockIdx.x * 32, n0 = blockIdx.y * 32;
#pragma unroll
    for (int r = 0; r < 4; r++) {
        int k = (tid >> 5) + r * 8;
        int n = tid & 31;
        t[k][n] = W[(size_t)(k0 + k) * N + n0 + n];
    }
    __syncthreads();
#pragma unroll
    for (int r = 0; r < 2; r++) {
        int n  = (tid >> 4) + r * 16;
        int kh = tid & 15;
        *(__half2*)&Wt[(size_t)(n0 + n) * KDIM + k0 + 2 * kh] =
            __floats2half2_rn(t[2 * kh][n], t[2 * kh + 1][n]);
    }
}

// ---------------------------------------------------------------------------
// HMMA GEMM: C[M,N] = A[M,K] @ Bt[N,K]^T + bias.  A,Bt fp16 in gmem.
// Tiles 128x128, BK=64, double-buffered (64KB dyn smem), 256 thr (8 warps:
// 4 M x 2 N), warp tile 32x64, ldmatrix fragment loads.
// MODE 0: scatter -> g_q/g_k fp16 [b,h,s,d], g_vt fp16 [b,h,d,s]
// MODE 1: fp32 row-major C + bias.
// ---------------------------------------------------------------------------
#define GEMM_SMEM (4 * 128 * 64 * 2)   // 65536 B

template<int MODE>
__global__ __launch_bounds__(256)
void gemm_hmma(const __half* __restrict__ A, const __half* __restrict__ Bt,
               const float* __restrict__ bias, float* __restrict__ C, int N)
{
    extern __shared__ char sm[];
    const unsigned sbase = smem_u32(sm);

    const int tid  = threadIdx.x;
    const int lane = tid & 31;
    const int w    = tid >> 5;
    const int g    = lane >> 2;
    const int tig  = lane & 3;
    const int moff = 32 * (w & 3);
    const int noff = 64 * (w >> 2);
    const int bm   = blockIdx.y * 128;
    const int bn   = blockIdx.x * 128;

    float acc[2][8][4];
#pragma unroll
    for (int mt = 0; mt < 2; mt++)
#pragma unroll
        for (int nt = 0; nt < 8; nt++)
#pragma unroll
            for (int i = 0; i < 4; i++) acc[mt][nt][i] = 0.f;

    uint4 pa[4], pb[4];
    auto ldg_chunk = [&](int k0) {
#pragma unroll
        for (int r = 0; r < 4; r++) {
            int idx = tid + r * 256;          // 0..1023
            int row = idx >> 3;               // 0..127
            int k8  = (idx & 7) * 8;
            pa[r] = *(const uint4*)&A [(size_t)(bm + row) * KDIM + k0 + k8];
            pb[r] = *(const uint4*)&Bt[(size_t)(bn + row) * KDIM + k0 + k8];
        }
    };
    auto sts_chunk = [&](int buf) {
        char* ap = sm + buf * 32768;
        char* bp = sm + buf * 32768 + 16384;
#pragma unroll
        for (int r = 0; r < 4; r++) {
            int idx = tid + r * 256;
            int row = idx >> 3;
            int k8  = (idx & 7) * 8;
            *(uint4*)(ap + 2 * fsw(row, k8)) = pa[r];
            *(uint4*)(bp + 2 * fsw(row, k8)) = pb[r];
        }
    };

    const int NCH = KDIM / 64;   // 16
    ldg_chunk(0);
    sts_chunk(0);
    __syncthreads();

    for (int c = 0; c < NCH; c++) {
        const int buf = c & 1;
        if (c + 1 < NCH) ldg_chunk((c + 1) * 64);

        const unsigned aB = sbase + buf * 32768;
        const unsigned bB = sbase + buf * 32768 + 16384;
#pragma unroll
        for (int ks = 0; ks < 4; ks++) {
            unsigned af[2][4], bf[8][2];
#pragma unroll
            for (int mt = 0; mt < 2; mt++)
                ldsmA(af[mt], aB, moff + 16 * mt, 16 * ks, lane);
#pragma unroll
            for (int ntp = 0; ntp < 4; ntp++) {
                unsigned t4[4];
                ldsmB(t4, bB, noff + 16 * ntp, 16 * ks, lane);
                bf[2 * ntp][0]     = t4[0]; bf[2 * ntp][1]     = t4[1];
                bf[2 * ntp + 1][0] = t4[2]; bf[2 * ntp + 1][1] = t4[3];
            }
#pragma unroll
            for (int mt = 0; mt < 2; mt++)
#pragma unroll
                for (int nt = 0; nt < 8; nt++)
                    mma_f16(acc[mt][nt], af[mt], bf[nt]);
        }
        if (c + 1 < NCH) sts_chunk(buf ^ 1);
        __syncthreads();
    }

    // epilogue
#pragma unroll
    for (int mt = 0; mt < 2; mt++) {
#pragma unroll
        for (int nt = 0; nt < 8; nt++) {
            const int n = bn + noff + 8 * nt + 2 * tig;
            const float bz0 = bias[n], bz1 = bias[n + 1];
#pragma unroll
            for (int half_i = 0; half_i < 2; half_i++) {
                const int m = bm + moff + 16 * mt + g + half_i * 8;
                float v0 = acc[mt][nt][half_i * 2 + 0] + bz0;
                float v1 = acc[mt][nt][half_i * 2 + 1] + bz1;
                if (MODE == 0) {
                    const int which = n >> 10;
                    const int hw = n & 1023;
                    const int hh = hw >> 6;
                    const int dd = hw & 63;
                    const int bI = m >> 11;
                    const int sI = m & 2047;
                    if (which == 2) {
                        const size_t base = ((size_t)(bI * NH + hh) * HD + dd) * SS + sI;
                        g_vt[base]      = __float2half_rn(v0);
                        g_vt[base + SS] = __float2half_rn(v1);
                    } else {
                        __half* dst = (which == 0) ? g_q : g_k;
                        *(__half2*)&dst[((size_t)(bI * NH + hh) * SS + sI) * HD + dd] =
                            __floats2half2_rn(v0, v1);
                    }
                } else {
                    *(float2*)&C[(size_t)m * N + n] = make_float2(v0, v1);
                }
            }
        }
    }
}

// ---------------------------------------------------------------------------
// Flash attention, fp16 MMA + ldmatrix. 128 q-rows/CTA, key tiles of 64,
// 8 warps. Q/K fp16 [b,h,s,d]; V fp16 [b,h,d,s]. P register-resident.
// ---------------------------------------------------------------------------
__global__ __launch_bounds__(256)
void flash_f16(const __half* __restrict__ Qg, const __half* __restrict__ Kg,
               const __half* __restrict__ Vtg, __half* __restrict__ Og)
{
    __shared__ __half Qs[128 * 64];
    __shared__ __half Ks[64 * 64];
    __shared__ __half Vs[64 * 64];   // [d][key]

    const int tid  = threadIdx.x;
    const int lane = tid & 31;
    const int w    = tid >> 5;
    const int g    = lane >> 2;
    const int tig  = lane & 3;

    const int qt = blockIdx.x;
    const int h  = blockIdx.y;
    const int b  = blockIdx.z;

    const __half* Qp  = Qg  + ((size_t)(b * NH + h) * SS + qt * 128) * HD;
    const __half* Kp  = Kg  + (size_t)(b * NH + h) * SS * HD;
    const __half* Vtp = Vtg + (size_t)(b * NH + h) * HD * SS;

    const unsigned qB = smem_u32(Qs);
    const unsigned kB = smem_u32(Ks);
    const unsigned vB = smem_u32(Vs);

#pragma unroll
    for (int r = 0; r < 4; r++) {
        int idx = tid + r * 256;
        int row = idx >> 3;
        int k8  = (idx & 7) * 8;
        uint4 v = *(const uint4*)&Qp[row * HD + k8];
        *(uint4*)&Qs[fsw(row, k8)] = v;
    }
    __syncthreads();

    unsigned qf[4][4];
#pragma unroll
    for (int dc = 0; dc < 4; dc++)
        ldsmA(qf[dc], qB, 16 * w, 16 * dc, lane);

    const float SCALE = 0.125f * 1.44269504088896f;

    float m0 = -1e30f, m1 = -1e30f, l0 = 0.f, l1 = 0.f;
    float Oa[8][4];
#pragma unroll
    for (int dt = 0; dt < 8; dt++)
#pragma unroll
        for (int i = 0; i < 4; i++) Oa[dt][i] = 0.f;

    uint4 kst[2], vst[2];
#pragma unroll
    for (int r = 0; r < 2; r++) {
        int idx = tid + r * 256;
        int row = idx >> 3;
        int k8  = (idx & 7) * 8;
        kst[r] = *(const uint4*)&Kp[row * HD + k8];
        vst[r] = *(const uint4*)&Vtp[(size_t)row * SS + k8];
    }

    for (int kt = 0; kt < SS / 64; kt++) {
        __syncthreads();
#pragma unroll
        for (int r = 0; r < 2; r++) {
            int idx = tid + r * 256;
            int row = idx >> 3;
            int k8  = (idx & 7) * 8;
            *(uint4*)&Ks[fsw(row, k8)] = kst[r];
            *(uint4*)&Vs[fsw(row, k8)] = vst[r];
        }
        __syncthreads();

        if (kt + 1 < SS / 64) {
            const __half* Kn = Kp + (size_t)(kt + 1) * 64 * HD;
#pragma unroll
            for (int r = 0; r < 2; r++) {
                int idx = tid + r * 256;
                int row = idx >> 3;
                int k8  = (idx & 7) * 8;
                kst[r] = *(const uint4*)&Kn[row * HD + k8];
                vst[r] = *(const uint4*)&Vtp[(size_t)row * SS + (kt + 1) * 64 + k8];
            }
        }

        // ---- S = Q @ K^T ----
        float S[8][4];
#pragma unroll
        for (int nt = 0; nt < 8; nt++)
#pragma unroll
            for (int i = 0; i < 4; i++) S[nt][i] = 0.f;
#pragma unroll
        for (int dc = 0; dc < 4; dc++) {
#pragma unroll
            for (int ntp = 0; ntp < 4; ntp++) {
                unsigned t4[4];
                ldsmB(t4, kB, 16 * ntp, 16 * dc, lane);
                mma_f16(S[2 * ntp],     qf[dc], t4);
                mma_f16(S[2 * ntp + 1], qf[dc], t4 + 2);
            }
        }

        // ---- online softmax ----
        float mx0 = S[0][0], mx1 = S[0][2];
#pragma unroll
        for (int nt = 0; nt < 8; nt++) {
            mx0 = fmaxf(mx0, fmaxf(S[nt][0], S[nt][1]));
            mx1 = fmaxf(mx1, fmaxf(S[nt][2], S[nt][3]));
        }
        mx0 = fmaxf(mx0, __shfl_xor_sync(0xffffffffu, mx0, 1));
        mx0 = fmaxf(mx0, __shfl_xor_sync(0xffffffffu, mx0, 2));
        mx1 = fmaxf(mx1, __shfl_xor_sync(0xffffffffu, mx1, 1));
        mx1 = fmaxf(mx1, __shfl_xor_sync(0xffffffffu, mx1, 2));

        const float mn0 = fmaxf(m0, mx0 * SCALE);
        const float mn1 = fmaxf(m1, mx1 * SCALE);
        const float al0 = ex2f(m0 - mn0);
        const float al1 = ex2f(m1 - mn1);
        m0 = mn0; m1 = mn1;

        float sum0 = 0.f, sum1 = 0.f;
#pragma unroll
        for (int nt = 0; nt < 8; nt++) {
            float p0 = ex2f(S[nt][0] * SCALE - mn0);
            float p1 = ex2f(S[nt][1] * SCALE - mn0);
            float p2 = ex2f(S[nt][2] * SCALE - mn1);
            float p3 = ex2f(S[nt][3] * SCALE - mn1);
            sum0 += p0 + p1;
            sum1 += p2 + p3;
            S[nt][0] = p0; S[nt][1] = p1; S[nt][2] = p2; S[nt][3] = p3;
        }
        sum0 += __shfl_xor_sync(0xffffffffu, sum0, 1);
        sum0 += __shfl_xor_sync(0xffffffffu, sum0, 2);
        sum1 += __shfl_xor_sync(0xffffffffu, sum1, 1);
        sum1 += __shfl_xor_sync(0xffffffffu, sum1, 2);
        l0 = l0 * al0 + sum0;
        l1 = l1 * al1 + sum1;

#pragma unroll
        for (int dt = 0; dt < 8; dt++) {
            Oa[dt][0] *= al0; Oa[dt][1] *= al0;
            Oa[dt][2] *= al1; Oa[dt][3] *= al1;
        }

        // ---- O += P @ V ----
#pragma unroll
        for (int kc = 0; kc < 4; kc++) {
            unsigned pf[4];
            pf[0] = pack2(S[2 * kc][0],     S[2 * kc][1]);
            pf[1] = pack2(S[2 * kc][2],     S[2 * kc][3]);
            pf[2] = pack2(S[2 * kc + 1][0], S[2 * kc + 1][1]);
            pf[3] = pack2(S[2 * kc + 1][2], S[2 * kc + 1][3]);
#pragma unroll
            for (int dtp = 0; dtp < 4; dtp++) {
                unsigned t4[4];
                ldsmB(t4, vB, 16 * dtp, 16 * kc, lane);
                mma_f16(Oa[2 * dtp],     pf, t4);
                mma_f16(Oa[2 * dtp + 1], pf, t4 + 2);
            }
        }
    }

    const float li0 = 1.f / l0;
    const float li1 = 1.f / l1;
    const int s0 = qt * 128 + 16 * w + g;
    const int s1 = s0 + 8;
#pragma unroll
    for (int dt = 0; dt < 8; dt++) {
        const int col = h * HD + 8 * dt + 2 * tig;
        *(__half2*)&Og[((size_t)(b * SS + s0)) * DIMV + col] =
            __floats2half2_rn(Oa[dt][0] * li0, Oa[dt][1] * li0);
        *(__half2*)&Og[((size_t)(b * SS + s1)) * DIMV + col] =
            __floats2half2_rn(Oa[dt][2] * li1, Oa[dt][3] * li1);
    }
}

// ---------------------------------------------------------------------------
extern "C" void kernel_launch(void* const* d_in, const int* in_sizes, int n_in,
                              void* d_out, int out_size)
{
    (void)in_sizes; (void)n_in; (void)out_size;
    const float* x     = (const float*)d_in[0];
    const float* W_qkv = (const float*)d_in[1];
    const float* b_qkv = (const float*)d_in[2];
    const float* W_out = (const float*)d_in[3];
    const float* b_out = (const float*)d_in[4];
    float* out = (float*)d_out;

    __half *xh, *wqt, *wot, *qb, *kb, *vtb, *ath;
    cudaGetSymbolAddress((void**)&xh,  g_xh);
    cudaGetSymbolAddress((void**)&wqt, g_wqt);
    cudaGetSymbolAddress((void**)&wot, g_wot);
    cudaGetSymbolAddress((void**)&qb,  g_q);
    cudaGetSymbolAddress((void**)&kb,  g_k);
    cudaGetSymbolAddress((void**)&vtb, g_vt);
    cudaGetSymbolAddress((void**)&ath, g_atth);

    static bool attr_set = false;
    if (!attr_set) {
        cudaFuncSetAttribute(gemm_hmma<0>, cudaFuncAttributeMaxDynamicSharedMemorySize, GEMM_SMEM);
        cudaFuncSetAttribute(gemm_hmma<1>, cudaFuncAttributeMaxDynamicSharedMemorySize, GEMM_SMEM);
        attr_set = true;
    }

    // 0. stage fp16 operands
    convert_x<<<MTOT * KDIM / 1024, 256>>>(x, xh);
    { dim3 g(KDIM / 32, 3 * DIMV / 32); transpose_w<<<g, 256>>>(W_qkv, wqt, 3 * DIMV); }
    { dim3 g(KDIM / 32, DIMV / 32);     transpose_w<<<g, 256>>>(W_out, wot, DIMV); }

    // 1. QKV GEMM -> fp16 Q/K head-layout + V^T
    { dim3 g(3 * DIMV / 128, MTOT / 128); gemm_hmma<0><<<g, 256, GEMM_SMEM>>>(xh, wqt, b_qkv, nullptr, 3 * DIMV); }
    // 2. Flash attention -> fp16 [b,s,dim]
    { dim3 g(SS / 128, NH, BB); flash_f16<<<g, 256>>>(qb, kb, vtb, ath); }
    // 3. Output projection -> fp32 out
    { dim3 g(DIMV / 128, MTOT / 128); gemm_hmma<1><<<g, 256, GEMM_SMEM>>>(ath, wot, b_out, out, DIMV); }
}

// round 12
// speedup vs baseline: 8.9548x; 1.2302x over previous
#include <cuda_runtime.h>
#include <cuda_fp16.h>
#include <math.h>

#define DIMV 1024
#define NH 16
#define HD 64
#define BB 2
#define SS 2048
#define MTOT (BB*SS)
#define KDIM 1024

// Scratch buffers.
__device__ __half g_xh  [MTOT*KDIM];        // x fp16 [M][K]
__device__ __half g_wqt [3*DIMV*KDIM];      // W_qkv^T fp16 [N=3072][K]
__device__ __half g_wot [DIMV*KDIM];        // W_out^T fp16 [N=1024][K]
__device__ __half g_q   [BB*NH*SS*HD];      // [b,h,s,d]  (pre-scaled by 1/8*log2e)
__device__ __half g_k   [BB*NH*SS*HD];      // [b,h,s,d]
__device__ __half g_vt  [BB*NH*HD*SS];      // [b,h,d,s]
__device__ __half g_atth[MTOT*DIMV];        // attention out fp16 [b*s][dim]

#define QSCALE (0.125f * 1.44269504088896f)

// ---------------------------------------------------------------------------
// helpers
// ---------------------------------------------------------------------------
__device__ __forceinline__ float ex2f(float x) {
    float y; asm("ex2.approx.f32 %0, %1;" : "=f"(y) : "f"(x)); return y;
}
__device__ __forceinline__ unsigned pack2(float a, float b) {
    __half2 h = __floats2half2_rn(a, b); return *(unsigned*)&h;
}
__device__ __forceinline__ void mma_f16(float* c, const unsigned* a, const unsigned* b) {
    asm volatile(
        "mma.sync.aligned.m16n8k16.row.col.f32.f16.f16.f32 "
        "{%0,%1,%2,%3}, {%4,%5,%6,%7}, {%8,%9}, {%0,%1,%2,%3};"
        : "+f"(c[0]), "+f"(c[1]), "+f"(c[2]), "+f"(c[3])
        : "r"(a[0]), "r"(a[1]), "r"(a[2]), "r"(a[3]), "r"(b[0]), "r"(b[1]));
}
// rows of 64 halves (128B), 16B-chunk XOR swizzle. Returns half-index.
__device__ __forceinline__ int fsw(int r, int k) {
    return r * 64 + (k & 7) + ((((k >> 3) ^ r) & 7)) * 8;
}
__device__ __forceinline__ unsigned smem_u32(const void* p) {
    unsigned a;
    asm("{ .reg .u64 t; cvta.to.shared.u64 t, %1; cvt.u32.u64 %0, t; }" : "=r"(a) : "l"(p));
    return a;
}
__device__ __forceinline__ void ldsm4(unsigned* r, unsigned addr) {
    asm volatile("ldmatrix.sync.aligned.m8n8.x4.shared.b16 {%0,%1,%2,%3}, [%4];"
                 : "=r"(r[0]), "=r"(r[1]), "=r"(r[2]), "=r"(r[3]) : "r"(addr));
}
// A-fragment (m16 x k16): regs = {mlo/klo, mhi/klo, mlo/khi, mhi/khi}
__device__ __forceinline__ void ldsmA(unsigned* r, unsigned tbase, int mbase, int kbase, int lane) {
    int row = mbase + (lane & 8) + (lane & 7);
    int col = kbase + (lane >> 4) * 8;
    ldsm4(r, tbase + 2 * fsw(row, col));
}
// B-fragment pair on [n][k] storage: regs = {b0,b1 of nt_lo, b0,b1 of nt_hi}
__device__ __forceinline__ void ldsmB(unsigned* r, unsigned tbase, int nbase, int kbase, int lane) {
    int row = nbase + ((lane & 16) >> 1) + (lane & 7);
    int col = kbase + ((lane >> 3) & 1) * 8;
    ldsm4(r, tbase + 2 * fsw(row, col));
}
__device__ __forceinline__ void cp16(unsigned dst, const void* src) {
    asm volatile("cp.async.cg.shared.global [%0], [%1], 16;" :: "r"(dst), "l"(src) : "memory");
}
__device__ __forceinline__ void cp_commit() {
    asm volatile("cp.async.commit_group;" ::: "memory");
}
template<int N> __device__ __forceinline__ void cp_wait() {
    asm volatile("cp.async.wait_group %0;" :: "n"(N) : "memory");
}

// ---------------------------------------------------------------------------
// Staging kernels
// ---------------------------------------------------------------------------
__global__ __launch_bounds__(256) void convert_x(const float* __restrict__ x, __half* __restrict__ xh) {
    int idx = blockIdx.x * 256 + threadIdx.x;      // float4 index
    float4 v = ((const float4*)x)[idx];
    ((uint2*)xh)[idx] = make_uint2(pack2(v.x, v.y), pack2(v.z, v.w));
}
__global__ __launch_bounds__(256) void transpose_w(const float* __restrict__ W, __half* __restrict__ Wt, int N) {
    __shared__ float t[32][33];
    const int tid = threadIdx.x;
    const int k0 = blockIdx.x * 32, n0 = blockIdx.y * 32;
#pragma unroll
    for (int r = 0; r < 4; r++) {
        int k = (tid >> 5) + r * 8;
        int n = tid & 31;
        t[k][n] = W[(size_t)(k0 + k) * N + n0 + n];
    }
    __syncthreads();
#pragma unroll
    for (int r = 0; r < 2; r++) {
        int n  = (tid >> 4) + r * 16;
        int kh = tid & 15;
        *(__half2*)&Wt[(size_t)(n0 + n) * KDIM + k0 + 2 * kh] =
            __floats2half2_rn(t[2 * kh][n], t[2 * kh + 1][n]);
    }
}

// ---------------------------------------------------------------------------
// HMMA GEMM: C[M,N] = A[M,K] @ Bt[N,K]^T + bias.  fp16 operands in gmem.
// Tiles 128x128, BK=64, 3-stage cp.async ring (96KB dyn smem), one sync/chunk,
// 256 thr (8 warps: 4M x 2N), warp tile 32x64, ldmatrix fragments.
// MODE 0: scatter -> g_q (pre-scaled) / g_k fp16 [b,h,s,d], g_vt fp16 [b,h,d,s]
// MODE 1: fp32 row-major C + bias.
// ---------------------------------------------------------------------------
#define GSTAGE 32768
#define GEMM_SMEM (3 * GSTAGE)   // 98304 B

template<int MODE>
__global__ __launch_bounds__(256)
void gemm_hmma(const __half* __restrict__ A, const __half* __restrict__ Bt,
               const float* __restrict__ bias, float* __restrict__ C, int N)
{
    extern __shared__ char sm[];
    const unsigned sbase = smem_u32(sm);

    const int tid  = threadIdx.x;
    const int lane = tid & 31;
    const int w    = tid >> 5;
    const int g    = lane >> 2;
    const int tig  = lane & 3;
    const int moff = 32 * (w & 3);
    const int noff = 64 * (w >> 2);
    const int bm   = blockIdx.y * 128;
    const int bn   = blockIdx.x * 128;

    float acc[2][8][4];
#pragma unroll
    for (int mt = 0; mt < 2; mt++)
#pragma unroll
        for (int nt = 0; nt < 8; nt++)
#pragma unroll
            for (int i = 0; i < 4; i++) acc[mt][nt][i] = 0.f;

    const int row = tid >> 3;            // 0..127 (fixed per thread)
    const int k8  = (tid & 7) * 8;
    const int swo = 2 * fsw(row, k8);    // byte offset within a tile

    auto cp_chunk = [&](int c, int buf) {
        const unsigned ab = sbase + buf * GSTAGE + swo;
        const unsigned bb = ab + 16384;
        const __half* ap = &A [(size_t)(bm + row) * KDIM + c * 64 + k8];
        const __half* bp = &Bt[(size_t)(bn + row) * KDIM + c * 64 + k8];
#pragma unroll
        for (int r = 0; r < 4; r++) {
            // rows row, row+32, row+64, row+96 share the same swizzle phase shape:
            // fsw(row+32*r, k) = fsw(row,k) + 32*r*64
            cp16(ab + r * 32 * 128, ap + (size_t)(32 * r) * KDIM);
            cp16(bb + r * 32 * 128, bp + (size_t)(32 * r) * KDIM);
        }
        cp_commit();
    };

    const int NCH = KDIM / 64;   // 16
    cp_chunk(0, 0);
    cp_chunk(1, 1);

    for (int c = 0; c < NCH; c++) {
        if (c < NCH - 1) cp_wait<1>(); else cp_wait<0>();
        __syncthreads();
        if (c + 2 < NCH) cp_chunk(c + 2, (c + 2) % 3);

        const int buf = c % 3;
        const unsigned aB = sbase + buf * GSTAGE;
        const unsigned bB = aB + 16384;
#pragma unroll
        for (int ks = 0; ks < 4; ks++) {
            unsigned af[2][4], bf[8][2];
#pragma unroll
            for (int mt = 0; mt < 2; mt++)
                ldsmA(af[mt], aB, moff + 16 * mt, 16 * ks, lane);
#pragma unroll
            for (int ntp = 0; ntp < 4; ntp++) {
                unsigned t4[4];
                ldsmB(t4, bB, noff + 16 * ntp, 16 * ks, lane);
                bf[2 * ntp][0]     = t4[0]; bf[2 * ntp][1]     = t4[1];
                bf[2 * ntp + 1][0] = t4[2]; bf[2 * ntp + 1][1] = t4[3];
            }
#pragma unroll
            for (int mt = 0; mt < 2; mt++)
#pragma unroll
                for (int nt = 0; nt < 8; nt++)
                    mma_f16(acc[mt][nt], af[mt], bf[nt]);
        }
    }

    // epilogue
#pragma unroll
    for (int mt = 0; mt < 2; mt++) {
#pragma unroll
        for (int nt = 0; nt < 8; nt++) {
            const int n = bn + noff + 8 * nt + 2 * tig;
            const float bz0 = bias[n], bz1 = bias[n + 1];
#pragma unroll
            for (int half_i = 0; half_i < 2; half_i++) {
                const int m = bm + moff + 16 * mt + g + half_i * 8;
                float v0 = acc[mt][nt][half_i * 2 + 0] + bz0;
                float v1 = acc[mt][nt][half_i * 2 + 1] + bz1;
                if (MODE == 0) {
                    const int which = n >> 10;
                    const int hw = n & 1023;
                    const int hh = hw >> 6;
                    const int dd = hw & 63;
                    const int bI = m >> 11;
                    const int sI = m & 2047;
                    if (which == 2) {
                        const size_t base = ((size_t)(bI * NH + hh) * HD + dd) * SS + sI;
                        g_vt[base]      = __float2half_rn(v0);
                        g_vt[base + SS] = __float2half_rn(v1);
                    } else if (which == 0) {
                        *(__half2*)&g_q[((size_t)(bI * NH + hh) * SS + sI) * HD + dd] =
                            __floats2half2_rn(v0 * QSCALE, v1 * QSCALE);
                    } else {
                        *(__half2*)&g_k[((size_t)(bI * NH + hh) * SS + sI) * HD + dd] =
                            __floats2half2_rn(v0, v1);
                    }
                } else {
                    *(float2*)&C[(size_t)m * N + n] = make_float2(v0, v1);
                }
            }
        }
    }
}

// ---------------------------------------------------------------------------
// Flash attention, fp16 MMA + ldmatrix + 3-stage cp.async K/V ring.
// 128 q-rows/CTA, key tiles of 64, 8 warps. Q pre-scaled (log2 domain).
// dyn smem: Qs 16KB + 3 x (K 8KB + V 8KB) = 64KB.
// ---------------------------------------------------------------------------
#define FQ 0
#define FK(s) (16384 + (s) * 16384)
#define FV(s) (16384 + (s) * 16384 + 8192)
#define FLASH_SMEM 65536

__global__ __launch_bounds__(256)
void flash_f16(const __half* __restrict__ Qg, const __half* __restrict__ Kg,
               const __half* __restrict__ Vtg, __half* __restrict__ Og)
{
    extern __shared__ char sm[];
    const unsigned sbase = smem_u32(sm);

    const int tid  = threadIdx.x;
    const int lane = tid & 31;
    const int w    = tid >> 5;
    const int g    = lane >> 2;
    const int tig  = lane & 3;

    const int qt = blockIdx.x;
    const int h  = blockIdx.y;
    const int b  = blockIdx.z;

    const __half* Qp  = Qg  + ((size_t)(b * NH + h) * SS + qt * 128) * HD;
    const __half* Kp  = Kg  + (size_t)(b * NH + h) * SS * HD;
    const __half* Vtp = Vtg + (size_t)(b * NH + h) * HD * SS;

    const int krow = tid >> 2;              // 0..63  (K/V tile row)
    const int kk8  = (tid & 3) * 16;        // two 16B chunks per thread per row
    auto cp_tile = [&](int kt, int s) {
        const unsigned kb = sbase + FK(s) + 2 * fsw(krow, kk8);
        const unsigned vb = sbase + FV(s) + 2 * fsw(krow, kk8);
        const __half* kp = &Kp [(size_t)(kt * 64 + krow) * HD + kk8];
        const __half* vp = &Vtp[(size_t)krow * SS + kt * 64 + kk8];
        cp16(kb, kp);                       cp16(vb, vp);
        cp16(kb + 2 * (fsw(krow, kk8 + 8) - fsw(krow, kk8)), kp + 8);
        cp16(vb + 2 * (fsw(krow, kk8 + 8) - fsw(krow, kk8)), vp + 8);
        cp_commit();
    };

    // ---- load Q tile (plain LDG/STS, once) ----
#pragma unroll
    for (int r = 0; r < 4; r++) {
        int idx = tid + r * 256;
        int row = idx >> 3;
        int k8  = (idx & 7) * 8;
        uint4 v = *(const uint4*)&Qp[row * HD + k8];
        *(uint4*)(sm + FQ + 2 * fsw(row, k8)) = v;
    }

    cp_tile(0, 0);
    cp_tile(1, 1);
    __syncthreads();   // Q visible

    unsigned qf[4][4];
#pragma unroll
    for (int dc = 0; dc < 4; dc++)
        ldsmA(qf[dc], sbase + FQ, 16 * w, 16 * dc, lane);

    float m0 = -1e30f, m1 = -1e30f, l0 = 0.f, l1 = 0.f;
    float Oa[8][4];
#pragma unroll
    for (int dt = 0; dt < 8; dt++)
#pragma unroll
        for (int i = 0; i < 4; i++) Oa[dt][i] = 0.f;

    const int NT = SS / 64;   // 32
    for (int kt = 0; kt < NT; kt++) {
        if (kt < NT - 1) cp_wait<1>(); else cp_wait<0>();
        __syncthreads();
        if (kt + 2 < NT) cp_tile(kt + 2, (kt + 2) % 3);

        const int buf = kt % 3;
        const unsigned kB = sbase + FK(buf);
        const unsigned vB = sbase + FV(buf);

        // ---- S = Q @ K^T (already log2-scaled via Q) ----
        float S[8][4];
#pragma unroll
        for (int nt = 0; nt < 8; nt++)
#pragma unroll
            for (int i = 0; i < 4; i++) S[nt][i] = 0.f;
#pragma unroll
        for (int dc = 0; dc < 4; dc++) {
#pragma unroll
            for (int ntp = 0; ntp < 4; ntp++) {
                unsigned t4[4];
                ldsmB(t4, kB, 16 * ntp, 16 * dc, lane);
                mma_f16(S[2 * ntp],     qf[dc], t4);
                mma_f16(S[2 * ntp + 1], qf[dc], t4 + 2);
            }
        }

        // ---- online softmax ----
        float mx0 = S[0][0], mx1 = S[0][2];
#pragma unroll
        for (int nt = 0; nt < 8; nt++) {
            mx0 = fmaxf(mx0, fmaxf(S[nt][0], S[nt][1]));
            mx1 = fmaxf(mx1, fmaxf(S[nt][2], S[nt][3]));
        }
        mx0 = fmaxf(mx0, __shfl_xor_sync(0xffffffffu, mx0, 1));
        mx0 = fmaxf(mx0, __shfl_xor_sync(0xffffffffu, mx0, 2));
        mx1 = fmaxf(mx1, __shfl_xor_sync(0xffffffffu, mx1, 1));
        mx1 = fmaxf(mx1, __shfl_xor_sync(0xffffffffu, mx1, 2));

        const float mn0 = fmaxf(m0, mx0);
        const float mn1 = fmaxf(m1, mx1);
        const float al0 = ex2f(m0 - mn0);
        const float al1 = ex2f(m1 - mn1);
        m0 = mn0; m1 = mn1;

        float sum0 = 0.f, sum1 = 0.f;
#pragma unroll
        for (int nt = 0; nt < 8; nt++) {
            float p0 = ex2f(S[nt][0] - mn0);
            float p1 = ex2f(S[nt][1] - mn0);
            float p2 = ex2f(S[nt][2] - mn1);
            float p3 = ex2f(S[nt][3] - mn1);
            sum0 += p0 + p1;
            sum1 += p2 + p3;
            S[nt][0] = p0; S[nt][1] = p1; S[nt][2] = p2; S[nt][3] = p3;
        }
        sum0 += __shfl_xor_sync(0xffffffffu, sum0, 1);
        sum0 += __shfl_xor_sync(0xffffffffu, sum0, 2);
        sum1 += __shfl_xor_sync(0xffffffffu, sum1, 1);
        sum1 += __shfl_xor_sync(0xffffffffu, sum1, 2);
        l0 = l0 * al0 + sum0;
        l1 = l1 * al1 + sum1;

#pragma unroll
        for (int dt = 0; dt < 8; dt++) {
            Oa[dt][0] *= al0; Oa[dt][1] *= al0;
            Oa[dt][2] *= al1; Oa[dt][3] *= al1;
        }

        // ---- O += P @ V ----
#pragma unroll
        for (int kc = 0; kc < 4; kc++) {
            unsigned pf[4];
            pf[0] = pack2(S[2 * kc][0],     S[2 * kc][1]);
            pf[1] = pack2(S[2 * kc][2],     S[2 * kc][3]);
            pf[2] = pack2(S[2 * kc + 1][0], S[2 * kc + 1][1]);
            pf[3] = pack2(S[2 * kc + 1][2], S[2 * kc + 1][3]);
#pragma unroll
            for (int dtp = 0; dtp < 4; dtp++) {
                unsigned t4[4];
                ldsmB(t4, vB, 16 * dtp, 16 * kc, lane);
                mma_f16(Oa[2 * dtp],     pf, t4);
                mma_f16(Oa[2 * dtp + 1], pf, t4 + 2);
            }
        }
    }

    const float li0 = 1.f / l0;
    const float li1 = 1.f / l1;
    const int s0 = qt * 128 + 16 * w + g;
    const int s1 = s0 + 8;
#pragma unroll
    for (int dt = 0; dt < 8; dt++) {
        const int col = h * HD + 8 * dt + 2 * tig;
        *(__half2*)&Og[((size_t)(b * SS + s0)) * DIMV + col] =
            __floats2half2_rn(Oa[dt][0] * li0, Oa[dt][1] * li0);
        *(__half2*)&Og[((size_t)(b * SS + s1)) * DIMV + col] =
            __floats2half2_rn(Oa[dt][2] * li1, Oa[dt][3] * li1);
    }
}

// ---------------------------------------------------------------------------
extern "C" void kernel_launch(void* const* d_in, const int* in_sizes, int n_in,
                              void* d_out, int out_size)
{
    (void)in_sizes; (void)n_in; (void)out_size;
    const float* x     = (const float*)d_in[0];
    const float* W_qkv = (const float*)d_in[1];
    const float* b_qkv = (const float*)d_in[2];
    const float* W_out = (const float*)d_in[3];
    const float* b_out = (const float*)d_in[4];
    float* out = (float*)d_out;

    __half *xh, *wqt, *wot, *qb, *kb, *vtb, *ath;
    cudaGetSymbolAddress((void**)&xh,  g_xh);
    cudaGetSymbolAddress((void**)&wqt, g_wqt);
    cudaGetSymbolAddress((void**)&wot, g_wot);
    cudaGetSymbolAddress((void**)&qb,  g_q);
    cudaGetSymbolAddress((void**)&kb,  g_k);
    cudaGetSymbolAddress((void**)&vtb, g_vt);
    cudaGetSymbolAddress((void**)&ath, g_atth);

    static bool attr_set = false;
    if (!attr_set) {
        cudaFuncSetAttribute(gemm_hmma<0>, cudaFuncAttributeMaxDynamicSharedMemorySize, GEMM_SMEM);
        cudaFuncSetAttribute(gemm_hmma<1>, cudaFuncAttributeMaxDynamicSharedMemorySize, GEMM_SMEM);
        cudaFuncSetAttribute(flash_f16,    cudaFuncAttributeMaxDynamicSharedMemorySize, FLASH_SMEM);
        attr_set = true;
    }

    // 0. stage fp16 operands
    convert_x<<<MTOT * KDIM / 1024, 256>>>(x, xh);
    { dim3 g(KDIM / 32, 3 * DIMV / 32); transpose_w<<<g, 256>>>(W_qkv, wqt, 3 * DIMV); }
    { dim3 g(KDIM / 32, DIMV / 32);     transpose_w<<<g, 256>>>(W_out, wot, DIMV); }

    // 1. QKV GEMM -> fp16 Q(prescaled)/K head-layout + V^T
    { dim3 g(3 * DIMV / 128, MTOT / 128); gemm_hmma<0><<<g, 256, GEMM_SMEM>>>(xh, wqt, b_qkv, nullptr, 3 * DIMV); }
    // 2. Flash attention -> fp16 [b,s,dim]
    { dim3 g(SS / 128, NH, BB); flash_f16<<<g, 256, FLASH_SMEM>>>(qb, kb, vtb, ath); }
    // 3. Output projection -> fp32 out
    { dim3 g(DIMV / 128, MTOT / 128); gemm_hmma<1><<<g, 256, GEMM_SMEM>>>(ath, wot, b_out, out, DIMV); }
}

// round 13
// speedup vs baseline: 9.3403x; 1.0430x over previous
#include <cuda_runtime.h>
#include <cuda_fp16.h>
#include <math.h>

#define DIMV 1024
#define NH 16
#define HD 64
#define BB 2
#define SS 2048
#define MTOT (BB*SS)
#define KDIM 1024

// Scratch buffers.
__device__ __half g_xh  [MTOT*KDIM];        // x fp16 [M][K]
__device__ __half g_wqt [3*DIMV*KDIM];      // W_qkv^T fp16 [N=3072][K]
__device__ __half g_wot [DIMV*KDIM];        // W_out^T fp16 [N=1024][K]
__device__ __half g_q   [BB*NH*SS*HD];      // [b,h,s,d]  (pre-scaled by 1/8*log2e)
__device__ __half g_k   [BB*NH*SS*HD];      // [b,h,s,d]
__device__ __half g_vt  [BB*NH*HD*SS];      // [b,h,d,s]
__device__ __half g_atth[MTOT*DIMV];        // attention out fp16 [b*s][dim]

#define QSCALE (0.125f * 1.44269504088896f)

// ---------------------------------------------------------------------------
// helpers
// ---------------------------------------------------------------------------
__device__ __forceinline__ float ex2f(float x) {
    float y; asm("ex2.approx.f32 %0, %1;" : "=f"(y) : "f"(x)); return y;
}
__device__ __forceinline__ unsigned pack2(float a, float b) {
    __half2 h = __floats2half2_rn(a, b); return *(unsigned*)&h;
}
// packed half2 = {lo=a, hi=b}
__device__ __forceinline__ unsigned cvt_h2(float a, float b) {
    unsigned r;
    asm("cvt.rn.f16x2.f32 %0, %1, %2;" : "=r"(r) : "f"(b), "f"(a));
    return r;
}
__device__ __forceinline__ unsigned ex2_h2(unsigned x) {
    unsigned r;
    asm("ex2.approx.f16x2 %0, %1;" : "=r"(r) : "r"(x));
    return r;
}
__device__ __forceinline__ void mma_f16(float* c, const unsigned* a, const unsigned* b) {
    asm volatile(
        "mma.sync.aligned.m16n8k16.row.col.f32.f16.f16.f32 "
        "{%0,%1,%2,%3}, {%4,%5,%6,%7}, {%8,%9}, {%0,%1,%2,%3};"
        : "+f"(c[0]), "+f"(c[1]), "+f"(c[2]), "+f"(c[3])
        : "r"(a[0]), "r"(a[1]), "r"(a[2]), "r"(a[3]), "r"(b[0]), "r"(b[1]));
}
// rows of 64 halves (128B), 16B-chunk XOR swizzle. Returns half-index.
__device__ __forceinline__ int fsw(int r, int k) {
    return r * 64 + (k & 7) + ((((k >> 3) ^ r) & 7)) * 8;
}
__device__ __forceinline__ unsigned smem_u32(const void* p) {
    unsigned a;
    asm("{ .reg .u64 t; cvta.to.shared.u64 t, %1; cvt.u32.u64 %0, t; }" : "=r"(a) : "l"(p));
    return a;
}
__device__ __forceinline__ void ldsm4(unsigned* r, unsigned addr) {
    asm volatile("ldmatrix.sync.aligned.m8n8.x4.shared.b16 {%0,%1,%2,%3}, [%4];"
                 : "=r"(r[0]), "=r"(r[1]), "=r"(r[2]), "=r"(r[3]) : "r"(addr));
}
// A-fragment (m16 x k16): regs = {mlo/klo, mhi/klo, mlo/khi, mhi/khi}
__device__ __forceinline__ void ldsmA(unsigned* r, unsigned tbase, int mbase, int kbase, int lane) {
    int row = mbase + (lane & 8) + (lane & 7);
    int col = kbase + (lane >> 4) * 8;
    ldsm4(r, tbase + 2 * fsw(row, col));
}
// B-fragment pair on [n][k] storage: regs = {b0,b1 of nt_lo, b0,b1 of nt_hi}
__device__ __forceinline__ void ldsmB(unsigned* r, unsigned tbase, int nbase, int kbase, int lane) {
    int row = nbase + ((lane & 16) >> 1) + (lane & 7);
    int col = kbase + ((lane >> 3) & 1) * 8;
    ldsm4(r, tbase + 2 * fsw(row, col));
}
__device__ __forceinline__ void cp16(unsigned dst, const void* src) {
    asm volatile("cp.async.cg.shared.global [%0], [%1], 16;" :: "r"(dst), "l"(src) : "memory");
}
__device__ __forceinline__ void cp_commit() {
    asm volatile("cp.async.commit_group;" ::: "memory");
}
template<int N> __device__ __forceinline__ void cp_wait() {
    asm volatile("cp.async.wait_group %0;" :: "n"(N) : "memory");
}

// ---------------------------------------------------------------------------
// Staging kernels
// ---------------------------------------------------------------------------
__global__ __launch_bounds__(256) void convert_x(const float* __restrict__ x, __half* __restrict__ xh) {
    int idx = blockIdx.x * 256 + threadIdx.x;      // float4 index
    float4 v = ((const float4*)x)[idx];
    ((uint2*)xh)[idx] = make_uint2(pack2(v.x, v.y), pack2(v.z, v.w));
}
__global__ __launch_bounds__(256) void transpose_w(const float* __restrict__ W, __half* __restrict__ Wt, int N) {
    __shared__ float t[32][33];
    const int tid = threadIdx.x;
    const int k0 = blockIdx.x * 32, n0 = blockIdx.y * 32;
#pragma unroll
    for (int r = 0; r < 4; r++) {
        int k = (tid >> 5) + r * 8;
        int n = tid & 31;
        t[k][n] = W[(size_t)(k0 + k) * N + n0 + n];
    }
    __syncthreads();
#pragma unroll
    for (int r = 0; r < 2; r++) {
        int n  = (tid >> 4) + r * 16;
        int kh = tid & 15;
        *(__half2*)&Wt[(size_t)(n0 + n) * KDIM + k0 + 2 * kh] =
            __floats2half2_rn(t[2 * kh][n], t[2 * kh + 1][n]);
    }
}

// ---------------------------------------------------------------------------
// HMMA GEMM: C[M,N] = A[M,K] @ Bt[N,K]^T + bias.  fp16 operands in gmem.
// Tiles 128x128, BK=64, 3-stage cp.async ring (96KB dyn smem), one sync/chunk,
// 256 thr (8 warps: 4M x 2N), warp tile 32x64, ldmatrix fragments.
// MODE 0: scatter -> g_q (pre-scaled) / g_k fp16 [b,h,s,d], g_vt fp16 [b,h,d,s]
// MODE 1: fp32 row-major C + bias.
// ---------------------------------------------------------------------------
#define GSTAGE 32768
#define GEMM_SMEM (3 * GSTAGE)   // 98304 B

template<int MODE>
__global__ __launch_bounds__(256)
void gemm_hmma(const __half* __restrict__ A, const __half* __restrict__ Bt,
               const float* __restrict__ bias, float* __restrict__ C, int N)
{
    extern __shared__ char sm[];
    const unsigned sbase = smem_u32(sm);

    const int tid  = threadIdx.x;
    const int lane = tid & 31;
    const int w    = tid >> 5;
    const int g    = lane >> 2;
    const int tig  = lane & 3;
    const int moff = 32 * (w & 3);
    const int noff = 64 * (w >> 2);
    const int bm   = blockIdx.y * 128;
    const int bn   = blockIdx.x * 128;

    float acc[2][8][4];
#pragma unroll
    for (int mt = 0; mt < 2; mt++)
#pragma unroll
        for (int nt = 0; nt < 8; nt++)
#pragma unroll
            for (int i = 0; i < 4; i++) acc[mt][nt][i] = 0.f;

    const int row = tid >> 3;            // 0..127 (fixed per thread)
    const int k8  = (tid & 7) * 8;
    const int swo = 2 * fsw(row, k8);    // byte offset within a tile

    auto cp_chunk = [&](int c, int buf) {
        const unsigned ab = sbase + buf * GSTAGE + swo;
        const unsigned bb = ab + 16384;
        const __half* ap = &A [(size_t)(bm + row) * KDIM + c * 64 + k8];
        const __half* bp = &Bt[(size_t)(bn + row) * KDIM + c * 64 + k8];
#pragma unroll
        for (int r = 0; r < 4; r++) {
            cp16(ab + r * 32 * 128, ap + (size_t)(32 * r) * KDIM);
            cp16(bb + r * 32 * 128, bp + (size_t)(32 * r) * KDIM);
        }
        cp_commit();
    };

    const int NCH = KDIM / 64;   // 16
    cp_chunk(0, 0);
    cp_chunk(1, 1);

    for (int c = 0; c < NCH; c++) {
        if (c < NCH - 1) cp_wait<1>(); else cp_wait<0>();
        __syncthreads();
        if (c + 2 < NCH) cp_chunk(c + 2, (c + 2) % 3);

        const int buf = c % 3;
        const unsigned aB = sbase + buf * GSTAGE;
        const unsigned bB = aB + 16384;
#pragma unroll
        for (int ks = 0; ks < 4; ks++) {
            unsigned af[2][4], bf[8][2];
#pragma unroll
            for (int mt = 0; mt < 2; mt++)
                ldsmA(af[mt], aB, moff + 16 * mt, 16 * ks, lane);
#pragma unroll
            for (int ntp = 0; ntp < 4; ntp++) {
                unsigned t4[4];
                ldsmB(t4, bB, noff + 16 * ntp, 16 * ks, lane);
                bf[2 * ntp][0]     = t4[0]; bf[2 * ntp][1]     = t4[1];
                bf[2 * ntp + 1][0] = t4[2]; bf[2 * ntp + 1][1] = t4[3];
            }
#pragma unroll
            for (int mt = 0; mt < 2; mt++)
#pragma unroll
                for (int nt = 0; nt < 8; nt++)
                    mma_f16(acc[mt][nt], af[mt], bf[nt]);
        }
    }

    // epilogue
#pragma unroll
    for (int mt = 0; mt < 2; mt++) {
#pragma unroll
        for (int nt = 0; nt < 8; nt++) {
            const int n = bn + noff + 8 * nt + 2 * tig;
            const float bz0 = bias[n], bz1 = bias[n + 1];
#pragma unroll
            for (int half_i = 0; half_i < 2; half_i++) {
                const int m = bm + moff + 16 * mt + g + half_i * 8;
                float v0 = acc[mt][nt][half_i * 2 + 0] + bz0;
                float v1 = acc[mt][nt][half_i * 2 + 1] + bz1;
                if (MODE == 0) {
                    const int which = n >> 10;
                    const int hw = n & 1023;
                    const int hh = hw >> 6;
                    const int dd = hw & 63;
                    const int bI = m >> 11;
                    const int sI = m & 2047;
                    if (which == 2) {
                        const size_t base = ((size_t)(bI * NH + hh) * HD + dd) * SS + sI;
                        g_vt[base]      = __float2half_rn(v0);
                        g_vt[base + SS] = __float2half_rn(v1);
                    } else if (which == 0) {
                        *(__half2*)&g_q[((size_t)(bI * NH + hh) * SS + sI) * HD + dd] =
                            __floats2half2_rn(v0 * QSCALE, v1 * QSCALE);
                    } else {
                        *(__half2*)&g_k[((size_t)(bI * NH + hh) * SS + sI) * HD + dd] =
                            __floats2half2_rn(v0, v1);
                    }
                } else {
                    *(float2*)&C[(size_t)m * N + n] = make_float2(v0, v1);
                }
            }
        }
    }
}

// ---------------------------------------------------------------------------
// Flash attention, fp16 MMA + ldmatrix + 3-stage cp.async K/V ring.
// 128 q-rows/CTA, key tiles of 64, 8 warps. Q pre-scaled (log2 domain).
// Softmax: ex2.approx.f16x2 (P born packed); row-sum l via ones-column MMA.
// dyn smem: Qs 16KB + 3 x (K 8KB + V 8KB) = 64KB.
// ---------------------------------------------------------------------------
#define FQ 0
#define FK(s) (16384 + (s) * 16384)
#define FV(s) (16384 + (s) * 16384 + 8192)
#define FLASH_SMEM 65536

__global__ __launch_bounds__(256)
void flash_f16(const __half* __restrict__ Qg, const __half* __restrict__ Kg,
               const __half* __restrict__ Vtg, __half* __restrict__ Og)
{
    extern __shared__ char sm[];
    const unsigned sbase = smem_u32(sm);

    const int tid  = threadIdx.x;
    const int lane = tid & 31;
    const int w    = tid >> 5;
    const int g    = lane >> 2;
    const int tig  = lane & 3;

    const int qt = blockIdx.x;
    const int h  = blockIdx.y;
    const int b  = blockIdx.z;

    const __half* Qp  = Qg  + ((size_t)(b * NH + h) * SS + qt * 128) * HD;
    const __half* Kp  = Kg  + (size_t)(b * NH + h) * SS * HD;
    const __half* Vtp = Vtg + (size_t)(b * NH + h) * HD * SS;

    const int krow = tid >> 2;              // 0..63  (K/V tile row)
    const int kk8  = (tid & 3) * 16;        // two 16B chunks per thread per row
    auto cp_tile = [&](int kt, int s) {
        const unsigned kb = sbase + FK(s) + 2 * fsw(krow, kk8);
        const unsigned vb = sbase + FV(s) + 2 * fsw(krow, kk8);
        const __half* kp = &Kp [(size_t)(kt * 64 + krow) * HD + kk8];
        const __half* vp = &Vtp[(size_t)krow * SS + kt * 64 + kk8];
        cp16(kb, kp);                       cp16(vb, vp);
        cp16(kb + 2 * (fsw(krow, kk8 + 8) - fsw(krow, kk8)), kp + 8);
        cp16(vb + 2 * (fsw(krow, kk8 + 8) - fsw(krow, kk8)), vp + 8);
        cp_commit();
    };

    // ---- load Q tile (plain LDG/STS, once) ----
#pragma unroll
    for (int r = 0; r < 4; r++) {
        int idx = tid + r * 256;
        int row = idx >> 3;
        int k8  = (idx & 7) * 8;
        uint4 v = *(const uint4*)&Qp[row * HD + k8];
        *(uint4*)(sm + FQ + 2 * fsw(row, k8)) = v;
    }

    cp_tile(0, 0);
    cp_tile(1, 1);
    __syncthreads();   // Q visible

    unsigned qf[4][4];
#pragma unroll
    for (int dc = 0; dc < 4; dc++)
        ldsmA(qf[dc], sbase + FQ, 16 * w, 16 * dc, lane);

    float m0 = -1e30f, m1 = -1e30f, l0 = 0.f, l1 = 0.f;
    float Oa[8][4];
#pragma unroll
    for (int dt = 0; dt < 8; dt++)
#pragma unroll
        for (int i = 0; i < 4; i++) Oa[dt][i] = 0.f;

    const unsigned ONES2[2] = { 0x3C003C00u, 0x3C003C00u };

    const int NT = SS / 64;   // 32
    for (int kt = 0; kt < NT; kt++) {
        if (kt < NT - 1) cp_wait<1>(); else cp_wait<0>();
        __syncthreads();
        if (kt + 2 < NT) cp_tile(kt + 2, (kt + 2) % 3);

        const int buf = kt % 3;
        const unsigned kB = sbase + FK(buf);
        const unsigned vB = sbase + FV(buf);

        // ---- S = Q @ K^T (already log2-scaled via Q) ----
        float S[8][4];
#pragma unroll
        for (int nt = 0; nt < 8; nt++)
#pragma unroll
            for (int i = 0; i < 4; i++) S[nt][i] = 0.f;
#pragma unroll
        for (int dc = 0; dc < 4; dc++) {
#pragma unroll
            for (int ntp = 0; ntp < 4; ntp++) {
                unsigned t4[4];
                ldsmB(t4, kB, 16 * ntp, 16 * dc, lane);
                mma_f16(S[2 * ntp],     qf[dc], t4);
                mma_f16(S[2 * ntp + 1], qf[dc], t4 + 2);
            }
        }

        // ---- online max ----
        float mx0 = S[0][0], mx1 = S[0][2];
#pragma unroll
        for (int nt = 0; nt < 8; nt++) {
            mx0 = fmaxf(mx0, fmaxf(S[nt][0], S[nt][1]));
            mx1 = fmaxf(mx1, fmaxf(S[nt][2], S[nt][3]));
        }
        mx0 = fmaxf(mx0, __shfl_xor_sync(0xffffffffu, mx0, 1));
        mx0 = fmaxf(mx0, __shfl_xor_sync(0xffffffffu, mx0, 2));
        mx1 = fmaxf(mx1, __shfl_xor_sync(0xffffffffu, mx1, 1));
        mx1 = fmaxf(mx1, __shfl_xor_sync(0xffffffffu, mx1, 2));

        const float mn0 = fmaxf(m0, mx0);
        const float mn1 = fmaxf(m1, mx1);
        const float al0 = ex2f(m0 - mn0);
        const float al1 = ex2f(m1 - mn1);
        m0 = mn0; m1 = mn1;

        // ---- P = 2^(S-m), computed in f16x2, born as packed A-fragments ----
        unsigned P[8][2];
#pragma unroll
        for (int nt = 0; nt < 8; nt++) {
            P[nt][0] = ex2_h2(cvt_h2(S[nt][0] - mn0, S[nt][1] - mn0));  // row g
            P[nt][1] = ex2_h2(cvt_h2(S[nt][2] - mn1, S[nt][3] - mn1));  // row g+8
        }

        // ---- rescale O ----
#pragma unroll
        for (int dt = 0; dt < 8; dt++) {
            Oa[dt][0] *= al0; Oa[dt][1] *= al0;
            Oa[dt][2] *= al1; Oa[dt][3] *= al1;
        }

        // ---- l partial via ones-MMA + O += P @ V ----
        float lacc[4] = {0.f, 0.f, 0.f, 0.f};
#pragma unroll
        for (int kc = 0; kc < 4; kc++) {
            unsigned pf[4];
            pf[0] = P[2 * kc][0];
            pf[1] = P[2 * kc][1];
            pf[2] = P[2 * kc + 1][0];
            pf[3] = P[2 * kc + 1][1];
            mma_f16(lacc, pf, ONES2);          // row sums -> lacc[0] (g), lacc[2] (g+8)
#pragma unroll
            for (int dtp = 0; dtp < 4; dtp++) {
                unsigned t4[4];
                ldsmB(t4, vB, 16 * dtp, 16 * kc, lane);
                mma_f16(Oa[2 * dtp],     pf, t4);
                mma_f16(Oa[2 * dtp + 1], pf, t4 + 2);
            }
        }
        l0 = l0 * al0 + lacc[0];
        l1 = l1 * al1 + lacc[2];
    }

    const float li0 = 1.f / l0;
    const float li1 = 1.f / l1;
    const int s0 = qt * 128 + 16 * w + g;
    const int s1 = s0 + 8;
#pragma unroll
    for (int dt = 0; dt < 8; dt++) {
        const int col = h * HD + 8 * dt + 2 * tig;
        *(__half2*)&Og[((size_t)(b * SS + s0)) * DIMV + col] =
            __floats2half2_rn(Oa[dt][0] * li0, Oa[dt][1] * li0);
        *(__half2*)&Og[((size_t)(b * SS + s1)) * DIMV + col] =
            __floats2half2_rn(Oa[dt][2] * li1, Oa[dt][3] * li1);
    }
}

// ---------------------------------------------------------------------------
extern "C" void kernel_launch(void* const* d_in, const int* in_sizes, int n_in,
                              void* d_out, int out_size)
{
    (void)in_sizes; (void)n_in; (void)out_size;
    const float* x     = (const float*)d_in[0];
    const float* W_qkv = (const float*)d_in[1];
    const float* b_qkv = (const float*)d_in[2];
    const float* W_out = (const float*)d_in[3];
    const float* b_out = (const float*)d_in[4];
    float* out = (float*)d_out;

    __half *xh, *wqt, *wot, *qb, *kb, *vtb, *ath;
    cudaGetSymbolAddress((void**)&xh,  g_xh);
    cudaGetSymbolAddress((void**)&wqt, g_wqt);
    cudaGetSymbolAddress((void**)&wot, g_wot);
    cudaGetSymbolAddress((void**)&qb,  g_q);
    cudaGetSymbolAddress((void**)&kb,  g_k);
    cudaGetSymbolAddress((void**)&vtb, g_vt);
    cudaGetSymbolAddress((void**)&ath, g_atth);

    static bool attr_set = false;
    if (!attr_set) {
        cudaFuncSetAttribute(gemm_hmma<0>, cudaFuncAttributeMaxDynamicSharedMemorySize, GEMM_SMEM);
        cudaFuncSetAttribute(gemm_hmma<1>, cudaFuncAttributeMaxDynamicSharedMemorySize, GEMM_SMEM);
        cudaFuncSetAttribute(flash_f16,    cudaFuncAttributeMaxDynamicSharedMemorySize, FLASH_SMEM);
        attr_set = true;
    }

    // 0. stage fp16 operands
    convert_x<<<MTOT * KDIM / 1024, 256>>>(x, xh);
    { dim3 g(KDIM / 32, 3 * DIMV / 32); transpose_w<<<g, 256>>>(W_qkv, wqt, 3 * DIMV); }
    { dim3 g(KDIM / 32, DIMV / 32);     transpose_w<<<g, 256>>>(W_out, wot, DIMV); }

    // 1. QKV GEMM -> fp16 Q(prescaled)/K head-layout + V^T
    { dim3 g(3 * DIMV / 128, MTOT / 128); gemm_hmma<0><<<g, 256, GEMM_SMEM>>>(xh, wqt, b_qkv, nullptr, 3 * DIMV); }
    // 2. Flash attention -> fp16 [b,s,dim]
    { dim3 g(SS / 128, NH, BB); flash_f16<<<g, 256, FLASH_SMEM>>>(qb, kb, vtb, ath); }
    // 3. Output projection -> fp32 out
    { dim3 g(DIMV / 128, MTOT / 128); gemm_hmma<1><<<g, 256, GEMM_SMEM>>>(ath, wot, b_out, out, DIMV); }
}